// round 1
// baseline (speedup 1.0000x reference)
#include <cuda_runtime.h>
#include <math.h>

#define N_TOK 2925
#define DM    1536
#define NH    12
#define HD    128
#define ATT_SCALE 0.08838834764831845f   // 1/sqrt(128)

// scratch (allocation-free workaround: __device__ globals)
__device__ float g_q[N_TOK * DM];
__device__ float g_k[N_TOK * DM];
__device__ float g_v[N_TOK * DM];
__device__ float g_o[N_TOK * DM];

// ---------------------------------------------------------------------------
// GEMM: C[M,N] = A[M,K] @ B[K,N] + bias[N]
// 128x128 block, BK=8, 256 threads, 8x8 microtile per thread.
// ---------------------------------------------------------------------------
__global__ __launch_bounds__(256) void gemm_bias_kernel(
    const float* __restrict__ A, const float* __restrict__ B,
    const float* __restrict__ bias, float* __restrict__ C,
    int M, int N, int K)
{
    __shared__ float As[8][128];   // transposed: As[k][m]
    __shared__ float Bs[8][128];   // Bs[k][n]

    const int tid = threadIdx.x;
    const int tx  = tid & 15;       // 0..15 (col group)
    const int ty  = tid >> 4;       // 0..15 (row group)
    const int row0 = blockIdx.y * 128;
    const int col0 = blockIdx.x * 128;

    float acc[8][8];
#pragma unroll
    for (int i = 0; i < 8; ++i)
#pragma unroll
        for (int j = 0; j < 8; ++j) acc[i][j] = 0.f;

    const int ar = tid >> 1;        // 0..127 A row in tile
    const int ac = (tid & 1) * 4;   // 0 or 4 (k offset)
    const int br = tid >> 5;        // 0..7   B row (k)
    const int bc = (tid & 31) * 4;  // 0..124 B col

    for (int k0 = 0; k0 < K; k0 += 8) {
        float4 av = make_float4(0.f, 0.f, 0.f, 0.f);
        if (row0 + ar < M)
            av = *(const float4*)(A + (size_t)(row0 + ar) * K + k0 + ac);
        As[ac + 0][ar] = av.x;
        As[ac + 1][ar] = av.y;
        As[ac + 2][ar] = av.z;
        As[ac + 3][ar] = av.w;

        *(float4*)(&Bs[br][bc]) =
            *(const float4*)(B + (size_t)(k0 + br) * N + col0 + bc);
        __syncthreads();

#pragma unroll
        for (int kk = 0; kk < 8; ++kk) {
            float4 a0 = *(float4*)&As[kk][ty * 8];
            float4 a1 = *(float4*)&As[kk][ty * 8 + 4];
            float4 b0 = *(float4*)&Bs[kk][tx * 8];
            float4 b1 = *(float4*)&Bs[kk][tx * 8 + 4];
            float a[8] = {a0.x, a0.y, a0.z, a0.w, a1.x, a1.y, a1.z, a1.w};
            float b[8] = {b0.x, b0.y, b0.z, b0.w, b1.x, b1.y, b1.z, b1.w};
#pragma unroll
            for (int i = 0; i < 8; ++i)
#pragma unroll
                for (int j = 0; j < 8; ++j)
                    acc[i][j] += a[i] * b[j];
        }
        __syncthreads();
    }

#pragma unroll
    for (int i = 0; i < 8; ++i) {
        int gr = row0 + ty * 8 + i;
        if (gr < M) {
#pragma unroll
            for (int j = 0; j < 8; ++j) {
                int gc = col0 + tx * 8 + j;
                C[(size_t)gr * N + gc] = acc[i][j] + bias[gc];
            }
        }
    }
}

// ---------------------------------------------------------------------------
// Fused RMSNorm (over full 1536) + 3D RoPE for Q and K. One block per token.
// ---------------------------------------------------------------------------
__global__ __launch_bounds__(256) void rms_rope_kernel(
    float* __restrict__ q, float* __restrict__ k,
    const float* __restrict__ qscale, const float* __restrict__ kscale,
    const float* __restrict__ ft, const float* __restrict__ fh,
    const float* __restrict__ fw)
{
    const int n   = blockIdx.x;
    const int tid = threadIdx.x;
    float* qr = q + (size_t)n * DM;
    float* kr = k + (size_t)n * DM;

    float sq = 0.f, sk = 0.f;
    for (int i = tid; i < DM; i += 256) {
        float a = qr[i]; sq += a * a;
        float b = kr[i]; sk += b * b;
    }
#pragma unroll
    for (int o = 16; o; o >>= 1) {
        sq += __shfl_xor_sync(0xffffffffu, sq, o);
        sk += __shfl_xor_sync(0xffffffffu, sk, o);
    }
    __shared__ float aq[8], ak[8];
    __shared__ float s_rq, s_rk;
    if ((tid & 31) == 0) { aq[tid >> 5] = sq; ak[tid >> 5] = sk; }
    __syncthreads();
    if (tid == 0) {
        float a = 0.f, b = 0.f;
#pragma unroll
        for (int i = 0; i < 8; ++i) { a += aq[i]; b += ak[i]; }
        s_rq = rsqrtf(a / (float)DM + 1e-6f);
        s_rk = rsqrtf(b / (float)DM + 1e-6f);
    }
    __syncthreads();
    const float rq = s_rq, rk = s_rk;

    const int wi = n % 15;
    const int hi = (n / 15) % 15;
    const int fi = n / 225;

    // 12 heads * 64 pairs = 768 pairs
    for (int pi = tid; pi < NH * (HD / 2); pi += 256) {
        const int head = pi >> 6;
        const int p    = pi & 63;
        float c, s;
        if (p < 22) {
            c = ft[(fi * 22 + p) * 2];
            s = ft[(fi * 22 + p) * 2 + 1];
        } else if (p < 43) {
            int pp = p - 22;
            c = fh[(hi * 21 + pp) * 2];
            s = fh[(hi * 21 + pp) * 2 + 1];
        } else {
            int pp = p - 43;
            c = fw[(wi * 21 + pp) * 2];
            s = fw[(wi * 21 + pp) * 2 + 1];
        }
        const int e0 = head * HD + 2 * p;
        const int e1 = e0 + 1;
        float x0 = qr[e0] * rq * qscale[e0];
        float x1 = qr[e1] * rq * qscale[e1];
        qr[e0] = x0 * c - x1 * s;
        qr[e1] = x0 * s + x1 * c;
        float y0 = kr[e0] * rk * kscale[e0];
        float y1 = kr[e1] * rk * kscale[e1];
        kr[e0] = y0 * c - y1 * s;
        kr[e1] = y0 * s + y1 * c;
    }
}

// ---------------------------------------------------------------------------
// Flash attention (fp32, online softmax). Block = (q-tile of 64, head).
// smem strides: Q/K/V rows padded to 129 floats, S rows to 65 (bank-conflict
// mitigation); column mapping per thread is strided by 16 -> conflict-free
// K reads in the S-GEMM and conflict-free V reads in the PV-GEMM.
// ---------------------------------------------------------------------------
#define QKV_STRIDE 129
#define S_STRIDE   65
#define ATT_SMEM_FLOATS (3 * 64 * QKV_STRIDE + 64 * S_STRIDE + 3 * 64)
#define ATT_SMEM_BYTES  (ATT_SMEM_FLOATS * 4)

__global__ __launch_bounds__(256) void attn_kernel(
    const float* __restrict__ Q, const float* __restrict__ Kg,
    const float* __restrict__ Vg, float* __restrict__ O)
{
    extern __shared__ float smf[];
    float* Qs   = smf;                       // 64 x 129
    float* Ks   = Qs + 64 * QKV_STRIDE;      // 64 x 129
    float* Vs   = Ks + 64 * QKV_STRIDE;      // 64 x 129
    float* Ss   = Vs + 64 * QKV_STRIDE;      // 64 x 65
    float* mrow = Ss + 64 * S_STRIDE;        // 64
    float* lrow = mrow + 64;                 // 64
    float* arow = lrow + 64;                 // 64

    const int tid  = threadIdx.x;
    const int head = blockIdx.y;
    const int q0   = blockIdx.x * 64;
    const int tx   = tid & 15;
    const int ty   = tid >> 4;
    const int r0   = ty * 4;

    // load Q tile
    for (int e = tid; e < 64 * 128; e += 256) {
        int r = e >> 7, d = e & 127;
        int t = q0 + r;
        Qs[r * QKV_STRIDE + d] =
            (t < N_TOK) ? Q[(size_t)t * DM + head * HD + d] : 0.f;
    }
    if (tid < 64) { mrow[tid] = -1e30f; lrow[tid] = 0.f; }

    float acc[4][8];
#pragma unroll
    for (int i = 0; i < 4; ++i)
#pragma unroll
        for (int j = 0; j < 8; ++j) acc[i][j] = 0.f;
    __syncthreads();

    const int nkt = (N_TOK + 63) / 64;
    for (int kt = 0; kt < nkt; ++kt) {
        const int kv0 = kt * 64;
        const int kvvalid = min(64, N_TOK - kv0);

        for (int e = tid; e < 64 * 128; e += 256) {
            int r = e >> 7, d = e & 127;
            int t = kv0 + r;
            float kk = 0.f, vv = 0.f;
            if (t < N_TOK) {
                kk = Kg[(size_t)t * DM + head * HD + d];
                vv = Vg[(size_t)t * DM + head * HD + d];
            }
            Ks[r * QKV_STRIDE + d] = kk;
            Vs[r * QKV_STRIDE + d] = vv;
        }
        __syncthreads();

        // S = (Q K^T) * scale  -> Ss
        float sacc[4][4];
#pragma unroll
        for (int i = 0; i < 4; ++i)
#pragma unroll
            for (int j = 0; j < 4; ++j) sacc[i][j] = 0.f;

        for (int d = 0; d < 128; ++d) {
            float a[4], b[4];
#pragma unroll
            for (int i = 0; i < 4; ++i) a[i] = Qs[(r0 + i) * QKV_STRIDE + d];
#pragma unroll
            for (int j = 0; j < 4; ++j) b[j] = Ks[(tx + 16 * j) * QKV_STRIDE + d];
#pragma unroll
            for (int i = 0; i < 4; ++i)
#pragma unroll
                for (int j = 0; j < 4; ++j) sacc[i][j] += a[i] * b[j];
        }
#pragma unroll
        for (int i = 0; i < 4; ++i)
#pragma unroll
            for (int j = 0; j < 4; ++j)
                Ss[(r0 + i) * S_STRIDE + tx + 16 * j] = sacc[i][j] * ATT_SCALE;
        __syncthreads();

        // online softmax: row = tid/4, 4 lanes cover 64 cols
        {
            const int row   = tid >> 2;
            const int part  = tid & 3;
            const int cbase = part * 16;
            float vmax = -1e30f;
#pragma unroll
            for (int c = 0; c < 16; ++c) {
                int cc = cbase + c;
                if (cc < kvvalid) vmax = fmaxf(vmax, Ss[row * S_STRIDE + cc]);
            }
            vmax = fmaxf(vmax, __shfl_xor_sync(0xffffffffu, vmax, 1));
            vmax = fmaxf(vmax, __shfl_xor_sync(0xffffffffu, vmax, 2));
            const float mold = mrow[row];
            const float mnew = fmaxf(mold, vmax);
            float lsum = 0.f;
#pragma unroll
            for (int c = 0; c < 16; ++c) {
                int cc = cbase + c;
                float p = (cc < kvvalid) ? __expf(Ss[row * S_STRIDE + cc] - mnew)
                                         : 0.f;
                Ss[row * S_STRIDE + cc] = p;
                lsum += p;
            }
            lsum += __shfl_xor_sync(0xffffffffu, lsum, 1);
            lsum += __shfl_xor_sync(0xffffffffu, lsum, 2);
            if (part == 0) {
                float al = __expf(mold - mnew);
                arow[row] = al;
                lrow[row] = lrow[row] * al + lsum;
                mrow[row] = mnew;
            }
        }
        __syncthreads();

        // rescale accumulators, then O += P @ V
#pragma unroll
        for (int i = 0; i < 4; ++i) {
            float al = arow[r0 + i];
#pragma unroll
            for (int j = 0; j < 8; ++j) acc[i][j] *= al;
        }
        for (int kk = 0; kk < 64; ++kk) {
            float p[4], v[8];
#pragma unroll
            for (int i = 0; i < 4; ++i) p[i] = Ss[(r0 + i) * S_STRIDE + kk];
#pragma unroll
            for (int j = 0; j < 8; ++j) v[j] = Vs[kk * QKV_STRIDE + tx + 16 * j];
#pragma unroll
            for (int i = 0; i < 4; ++i)
#pragma unroll
                for (int j = 0; j < 8; ++j) acc[i][j] += p[i] * v[j];
        }
        __syncthreads();
    }

#pragma unroll
    for (int i = 0; i < 4; ++i) {
        int t = q0 + r0 + i;
        if (t < N_TOK) {
            float inv = 1.f / lrow[r0 + i];
#pragma unroll
            for (int j = 0; j < 8; ++j)
                O[(size_t)t * DM + head * HD + tx + 16 * j] = acc[i][j] * inv;
        }
    }
}

// ---------------------------------------------------------------------------
extern "C" void kernel_launch(void* const* d_in, const int* in_sizes, int n_in,
                              void* d_out, int out_size)
{
    const float* x  = (const float*)d_in[0];
    const float* Wq = (const float*)d_in[1];
    const float* bq = (const float*)d_in[2];
    const float* Wk = (const float*)d_in[3];
    const float* bk = (const float*)d_in[4];
    const float* Wv = (const float*)d_in[5];
    const float* bv = (const float*)d_in[6];
    const float* Wo = (const float*)d_in[7];
    const float* bo = (const float*)d_in[8];
    const float* qs = (const float*)d_in[9];
    const float* ks = (const float*)d_in[10];
    const float* ft = (const float*)d_in[11];
    const float* fh = (const float*)d_in[12];
    const float* fw = (const float*)d_in[13];
    float* out = (float*)d_out;

    float *pq, *pk, *pv, *po;
    cudaGetSymbolAddress((void**)&pq, g_q);
    cudaGetSymbolAddress((void**)&pk, g_k);
    cudaGetSymbolAddress((void**)&pv, g_v);
    cudaGetSymbolAddress((void**)&po, g_o);

    cudaFuncSetAttribute(attn_kernel,
                         cudaFuncAttributeMaxDynamicSharedMemorySize,
                         ATT_SMEM_BYTES);

    dim3 gg(DM / 128, (N_TOK + 127) / 128);
    gemm_bias_kernel<<<gg, 256>>>(x, Wq, bq, pq, N_TOK, DM, DM);
    gemm_bias_kernel<<<gg, 256>>>(x, Wk, bk, pk, N_TOK, DM, DM);
    gemm_bias_kernel<<<gg, 256>>>(x, Wv, bv, pv, N_TOK, DM, DM);

    rms_rope_kernel<<<N_TOK, 256>>>(pq, pk, qs, ks, ft, fh, fw);

    dim3 ga((N_TOK + 63) / 64, NH);
    attn_kernel<<<ga, 256, ATT_SMEM_BYTES>>>(pq, pk, pv, po);

    gemm_bias_kernel<<<gg, 256>>>(po, Wo, bo, out, N_TOK, DM, DM);
}

// round 2
// speedup vs baseline: 3.2751x; 3.2751x over previous
#include <cuda_runtime.h>
#include <math.h>

#define N_TOK 2925
#define DM    1536
#define NH    12
#define HD    128
#define ATT_SCALE 0.08838834764831845f   // 1/sqrt(128)

// scratch (allocation-free workaround: __device__ globals)
__device__ float g_q[N_TOK * DM];
__device__ float g_k[N_TOK * DM];
__device__ float g_v[N_TOK * DM];
__device__ float g_o[N_TOK * DM];

// ---------------------------------------------------------------------------
// helpers
// ---------------------------------------------------------------------------
__device__ __forceinline__ unsigned f2tf32(float x) {
    unsigned r;
    asm("cvt.rna.tf32.f32 %0, %1;" : "=r"(r) : "f"(x));
    return r;
}

__device__ __forceinline__ void mma_tf32(float* d, const unsigned* a,
                                         const unsigned* b) {
    asm volatile(
        "mma.sync.aligned.m16n8k8.row.col.f32.tf32.tf32.f32 "
        "{%0,%1,%2,%3}, {%4,%5,%6,%7}, {%8,%9}, {%0,%1,%2,%3};"
        : "+f"(d[0]), "+f"(d[1]), "+f"(d[2]), "+f"(d[3])
        : "r"(a[0]), "r"(a[1]), "r"(a[2]), "r"(a[3]), "r"(b[0]), "r"(b[1]));
}

// ---------------------------------------------------------------------------
// tf32 tensor-core GEMM: C[M,1536] = A[M,1536] @ B[1536,1536] + bias
// block tile 128x128, BK=32, 256 threads (8 warps, 4m x 2n), warp tile 32x64
// ---------------------------------------------------------------------------
#define SA_STRIDE 36     // As[m][k], m rows, stride 36 floats
#define SB_STRIDE 136    // Bs[k][n], k rows, stride 136 floats

__global__ __launch_bounds__(256) void gemm_tf32_kernel(
    const float* __restrict__ A, const float* __restrict__ B,
    const float* __restrict__ bias, float* __restrict__ C, int M)
{
    __shared__ float As[128 * SA_STRIDE];
    __shared__ float Bs[32 * SB_STRIDE];
    const unsigned* Asu = (const unsigned*)As;
    const unsigned* Bsu = (const unsigned*)Bs;

    const int tid  = threadIdx.x;
    const int lane = tid & 31;
    const int warp = tid >> 5;
    const int wm   = warp & 3;   // 0..3 -> m offset 32*wm
    const int wn   = warp >> 2;  // 0..1 -> n offset 64*wn
    const int qr   = lane >> 2;
    const int qc   = lane & 3;

    const int row0 = blockIdx.y * 128;
    const int col0 = blockIdx.x * 128;

    float acc[2][8][4];
#pragma unroll
    for (int i = 0; i < 2; ++i)
#pragma unroll
        for (int j = 0; j < 8; ++j)
#pragma unroll
            for (int t = 0; t < 4; ++t) acc[i][j][t] = 0.f;

    for (int k0 = 0; k0 < DM; k0 += 32) {
        // load A tile (128x32) -> As[m][k] (tf32-rounded)
#pragma unroll
        for (int l = 0; l < 4; ++l) {
            int idx = tid + l * 256;         // 0..1023
            int r   = idx >> 3;              // 0..127
            int c4  = (idx & 7) * 4;         // 0..28
            float4 v = make_float4(0.f, 0.f, 0.f, 0.f);
            if (row0 + r < M)
                v = *(const float4*)(A + (size_t)(row0 + r) * DM + k0 + c4);
            float* p = &As[r * SA_STRIDE + c4];
            p[0] = __uint_as_float(f2tf32(v.x));
            p[1] = __uint_as_float(f2tf32(v.y));
            p[2] = __uint_as_float(f2tf32(v.z));
            p[3] = __uint_as_float(f2tf32(v.w));
        }
        // load B tile (32x128) -> Bs[k][n]
#pragma unroll
        for (int l = 0; l < 4; ++l) {
            int idx = tid + l * 256;
            int r   = idx >> 5;              // 0..31
            int c4  = (idx & 31) * 4;        // 0..124
            float4 v = *(const float4*)(B + (size_t)(k0 + r) * DM + col0 + c4);
            float* p = &Bs[r * SB_STRIDE + c4];
            p[0] = __uint_as_float(f2tf32(v.x));
            p[1] = __uint_as_float(f2tf32(v.y));
            p[2] = __uint_as_float(f2tf32(v.z));
            p[3] = __uint_as_float(f2tf32(v.w));
        }
        __syncthreads();

#pragma unroll
        for (int ks = 0; ks < 4; ++ks) {
            const int kb = ks * 8;
            unsigned a[2][4];
#pragma unroll
            for (int mi = 0; mi < 2; ++mi) {
                int r = wm * 32 + mi * 16 + qr;
                a[mi][0] = Asu[r * SA_STRIDE + kb + qc];
                a[mi][1] = Asu[(r + 8) * SA_STRIDE + kb + qc];
                a[mi][2] = Asu[r * SA_STRIDE + kb + qc + 4];
                a[mi][3] = Asu[(r + 8) * SA_STRIDE + kb + qc + 4];
            }
            unsigned b[8][2];
#pragma unroll
            for (int ni = 0; ni < 8; ++ni) {
                int col = wn * 64 + ni * 8 + qr;
                b[ni][0] = Bsu[(kb + qc) * SB_STRIDE + col];
                b[ni][1] = Bsu[(kb + qc + 4) * SB_STRIDE + col];
            }
#pragma unroll
            for (int mi = 0; mi < 2; ++mi)
#pragma unroll
                for (int ni = 0; ni < 8; ++ni)
                    mma_tf32(acc[mi][ni], a[mi], b[ni]);
        }
        __syncthreads();
    }

    // store C
#pragma unroll
    for (int mi = 0; mi < 2; ++mi) {
#pragma unroll
        for (int ni = 0; ni < 8; ++ni) {
            int col = col0 + wn * 64 + ni * 8 + 2 * qc;
            int r1  = row0 + wm * 32 + mi * 16 + qr;
            int r2  = r1 + 8;
            if (r1 < M) {
                float2 v = make_float2(acc[mi][ni][0] + bias[col],
                                       acc[mi][ni][1] + bias[col + 1]);
                *(float2*)(C + (size_t)r1 * DM + col) = v;
            }
            if (r2 < M) {
                float2 v = make_float2(acc[mi][ni][2] + bias[col],
                                       acc[mi][ni][3] + bias[col + 1]);
                *(float2*)(C + (size_t)r2 * DM + col) = v;
            }
        }
    }
}

// ---------------------------------------------------------------------------
// Fused RMSNorm + 3D RoPE for Q and K. One block per token. (unchanged)
// ---------------------------------------------------------------------------
__global__ __launch_bounds__(256) void rms_rope_kernel(
    float* __restrict__ q, float* __restrict__ k,
    const float* __restrict__ qscale, const float* __restrict__ kscale,
    const float* __restrict__ ft, const float* __restrict__ fh,
    const float* __restrict__ fw)
{
    const int n   = blockIdx.x;
    const int tid = threadIdx.x;
    float* qr = q + (size_t)n * DM;
    float* kr = k + (size_t)n * DM;

    float sq = 0.f, sk = 0.f;
    for (int i = tid; i < DM; i += 256) {
        float a = qr[i]; sq += a * a;
        float b = kr[i]; sk += b * b;
    }
#pragma unroll
    for (int o = 16; o; o >>= 1) {
        sq += __shfl_xor_sync(0xffffffffu, sq, o);
        sk += __shfl_xor_sync(0xffffffffu, sk, o);
    }
    __shared__ float aq[8], ak[8];
    __shared__ float s_rq, s_rk;
    if ((tid & 31) == 0) { aq[tid >> 5] = sq; ak[tid >> 5] = sk; }
    __syncthreads();
    if (tid == 0) {
        float a = 0.f, b = 0.f;
#pragma unroll
        for (int i = 0; i < 8; ++i) { a += aq[i]; b += ak[i]; }
        s_rq = rsqrtf(a / (float)DM + 1e-6f);
        s_rk = rsqrtf(b / (float)DM + 1e-6f);
    }
    __syncthreads();
    const float rq = s_rq, rk = s_rk;

    const int wi = n % 15;
    const int hi = (n / 15) % 15;
    const int fi = n / 225;

    for (int pi = tid; pi < NH * (HD / 2); pi += 256) {
        const int head = pi >> 6;
        const int p    = pi & 63;
        float c, s;
        if (p < 22) {
            c = ft[(fi * 22 + p) * 2];
            s = ft[(fi * 22 + p) * 2 + 1];
        } else if (p < 43) {
            int pp = p - 22;
            c = fh[(hi * 21 + pp) * 2];
            s = fh[(hi * 21 + pp) * 2 + 1];
        } else {
            int pp = p - 43;
            c = fw[(wi * 21 + pp) * 2];
            s = fw[(wi * 21 + pp) * 2 + 1];
        }
        const int e0 = head * HD + 2 * p;
        const int e1 = e0 + 1;
        float x0 = qr[e0] * rq * qscale[e0];
        float x1 = qr[e1] * rq * qscale[e1];
        qr[e0] = x0 * c - x1 * s;
        qr[e1] = x0 * s + x1 * c;
        float y0 = kr[e0] * rk * kscale[e0];
        float y1 = kr[e1] * rk * kscale[e1];
        kr[e0] = y0 * c - y1 * s;
        kr[e1] = y0 * s + y1 * c;
    }
}

// ---------------------------------------------------------------------------
// Flash attention with tf32 tensor cores.
// Block = (q-tile of 64, head). 256 threads (8 warps, 4m x 2n).
// S-GEMM warp tile 16x32; PV warp tile 16x64.
// ---------------------------------------------------------------------------
#define Q_STRIDE 132
#define K_STRIDE 132
#define V_STRIDE 136
#define S_STRIDE 68
#define ATT_SMEM_FLOATS (64*Q_STRIDE + 64*K_STRIDE + 64*V_STRIDE + 64*S_STRIDE + 3*64)
#define ATT_SMEM_BYTES  (ATT_SMEM_FLOATS * 4)

__global__ __launch_bounds__(256) void attn_kernel(
    const float* __restrict__ Q, const float* __restrict__ Kg,
    const float* __restrict__ Vg, float* __restrict__ O)
{
    extern __shared__ float smf[];
    float* Qs   = smf;                       // 64 x 132 (tf32)
    float* Ks   = Qs + 64 * Q_STRIDE;        // 64 x 132 (tf32)
    float* Vs   = Ks + 64 * K_STRIDE;        // 64 x 136 (tf32)
    float* Ss   = Vs + 64 * V_STRIDE;        // 64 x 68  (scores fp32 -> p tf32)
    float* mrow = Ss + 64 * S_STRIDE;
    float* lrow = mrow + 64;
    float* arow = lrow + 64;
    const unsigned* Qsu = (const unsigned*)Qs;
    const unsigned* Ksu = (const unsigned*)Ks;
    const unsigned* Vsu = (const unsigned*)Vs;
    const unsigned* Ssu = (const unsigned*)Ss;

    const int tid  = threadIdx.x;
    const int lane = tid & 31;
    const int warp = tid >> 5;
    const int wm   = warp & 3;    // m offset 16*wm
    const int wn   = warp >> 2;   // n offset 32*wn (S) / 64*wn (PV)
    const int qr   = lane >> 2;
    const int qc   = lane & 3;
    const int head = blockIdx.y;
    const int q0   = blockIdx.x * 64;

    // load Q tile (64 x 128), tf32-rounded
#pragma unroll
    for (int l = 0; l < 8; ++l) {
        int idx = tid + l * 256;          // 0..2047 float4s
        int r   = idx >> 5;               // 0..63
        int c4  = (idx & 31) * 4;         // 0..124
        int t   = q0 + r;
        float4 v = make_float4(0.f, 0.f, 0.f, 0.f);
        if (t < N_TOK)
            v = *(const float4*)(Q + (size_t)t * DM + head * HD + c4);
        float* p = &Qs[r * Q_STRIDE + c4];
        p[0] = __uint_as_float(f2tf32(v.x));
        p[1] = __uint_as_float(f2tf32(v.y));
        p[2] = __uint_as_float(f2tf32(v.z));
        p[3] = __uint_as_float(f2tf32(v.w));
    }
    if (tid < 64) { mrow[tid] = -1e30f; lrow[tid] = 0.f; }

    float acc_o[8][4];
#pragma unroll
    for (int j = 0; j < 8; ++j)
#pragma unroll
        for (int t = 0; t < 4; ++t) acc_o[j][t] = 0.f;
    __syncthreads();

    const int nkt = (N_TOK + 63) / 64;
    for (int kt = 0; kt < nkt; ++kt) {
        const int kv0 = kt * 64;
        const int kvvalid = min(64, N_TOK - kv0);

        // load K/V tiles
#pragma unroll
        for (int l = 0; l < 8; ++l) {
            int idx = tid + l * 256;
            int r   = idx >> 5;
            int c4  = (idx & 31) * 4;
            int t   = kv0 + r;
            float4 kv = make_float4(0.f, 0.f, 0.f, 0.f);
            float4 vv = make_float4(0.f, 0.f, 0.f, 0.f);
            if (t < N_TOK) {
                kv = *(const float4*)(Kg + (size_t)t * DM + head * HD + c4);
                vv = *(const float4*)(Vg + (size_t)t * DM + head * HD + c4);
            }
            float* pk = &Ks[r * K_STRIDE + c4];
            pk[0] = __uint_as_float(f2tf32(kv.x));
            pk[1] = __uint_as_float(f2tf32(kv.y));
            pk[2] = __uint_as_float(f2tf32(kv.z));
            pk[3] = __uint_as_float(f2tf32(kv.w));
            float* pv = &Vs[r * V_STRIDE + c4];
            pv[0] = __uint_as_float(f2tf32(vv.x));
            pv[1] = __uint_as_float(f2tf32(vv.y));
            pv[2] = __uint_as_float(f2tf32(vv.z));
            pv[3] = __uint_as_float(f2tf32(vv.w));
        }
        __syncthreads();

        // S = Q @ K^T : warp tile 16(m) x 32(n), 4 n-frags, 16 k-steps
        float acc_s[4][4];
#pragma unroll
        for (int j = 0; j < 4; ++j)
#pragma unroll
            for (int t = 0; t < 4; ++t) acc_s[j][t] = 0.f;

#pragma unroll
        for (int ks = 0; ks < 16; ++ks) {
            const int kb = ks * 8;
            unsigned a[4];
            {
                int r = wm * 16 + qr;
                a[0] = Qsu[r * Q_STRIDE + kb + qc];
                a[1] = Qsu[(r + 8) * Q_STRIDE + kb + qc];
                a[2] = Qsu[r * Q_STRIDE + kb + qc + 4];
                a[3] = Qsu[(r + 8) * Q_STRIDE + kb + qc + 4];
            }
#pragma unroll
            for (int ni = 0; ni < 4; ++ni) {
                unsigned b[2];
                int n = wn * 32 + ni * 8 + qr;
                b[0] = Ksu[n * K_STRIDE + kb + qc];
                b[1] = Ksu[n * K_STRIDE + kb + qc + 4];
                mma_tf32(acc_s[ni], a, b);
            }
        }
        // store scaled scores to Ss (fp32)
#pragma unroll
        for (int ni = 0; ni < 4; ++ni) {
            int col = wn * 32 + ni * 8 + 2 * qc;
            int r1  = wm * 16 + qr;
            *(float2*)(&Ss[r1 * S_STRIDE + col]) =
                make_float2(acc_s[ni][0] * ATT_SCALE, acc_s[ni][1] * ATT_SCALE);
            *(float2*)(&Ss[(r1 + 8) * S_STRIDE + col]) =
                make_float2(acc_s[ni][2] * ATT_SCALE, acc_s[ni][3] * ATT_SCALE);
        }
        __syncthreads();

        // online softmax: row = tid/4, 4 lanes cover 64 cols; p stored tf32
        {
            const int row   = tid >> 2;
            const int part  = tid & 3;
            const int cbase = part * 16;
            float vmax = -1e30f;
#pragma unroll
            for (int c = 0; c < 16; ++c) {
                int cc = cbase + c;
                if (cc < kvvalid) vmax = fmaxf(vmax, Ss[row * S_STRIDE + cc]);
            }
            vmax = fmaxf(vmax, __shfl_xor_sync(0xffffffffu, vmax, 1));
            vmax = fmaxf(vmax, __shfl_xor_sync(0xffffffffu, vmax, 2));
            const float mold = mrow[row];
            const float mnew = fmaxf(mold, vmax);
            float lsum = 0.f;
#pragma unroll
            for (int c = 0; c < 16; ++c) {
                int cc = cbase + c;
                float p = (cc < kvvalid)
                              ? __expf(Ss[row * S_STRIDE + cc] - mnew)
                              : 0.f;
                Ss[row * S_STRIDE + cc] = __uint_as_float(f2tf32(p));
                lsum += p;
            }
            lsum += __shfl_xor_sync(0xffffffffu, lsum, 1);
            lsum += __shfl_xor_sync(0xffffffffu, lsum, 2);
            if (part == 0) {
                float al = __expf(mold - mnew);
                arow[row] = al;
                lrow[row] = lrow[row] * al + lsum;
                mrow[row] = mnew;
            }
        }
        __syncthreads();

        // rescale acc_o, then O += P @ V : warp tile 16(m) x 64(n), 8 k-steps
        {
            int r1 = wm * 16 + qr;
            float a1 = arow[r1], a2 = arow[r1 + 8];
#pragma unroll
            for (int j = 0; j < 8; ++j) {
                acc_o[j][0] *= a1; acc_o[j][1] *= a1;
                acc_o[j][2] *= a2; acc_o[j][3] *= a2;
            }
        }
#pragma unroll
        for (int ks = 0; ks < 8; ++ks) {
            const int kb = ks * 8;
            unsigned a[4];
            {
                int r = wm * 16 + qr;
                a[0] = Ssu[r * S_STRIDE + kb + qc];
                a[1] = Ssu[(r + 8) * S_STRIDE + kb + qc];
                a[2] = Ssu[r * S_STRIDE + kb + qc + 4];
                a[3] = Ssu[(r + 8) * S_STRIDE + kb + qc + 4];
            }
#pragma unroll
            for (int ni = 0; ni < 8; ++ni) {
                unsigned b[2];
                int d = wn * 64 + ni * 8 + qr;
                b[0] = Vsu[(kb + qc) * V_STRIDE + d];
                b[1] = Vsu[(kb + qc + 4) * V_STRIDE + d];
                mma_tf32(acc_o[ni], a, b);
            }
        }
        __syncthreads();
    }

    // write O = acc / l
    {
        int r1 = wm * 16 + qr;
        int t1 = q0 + r1, t2 = t1 + 8;
        float inv1 = (t1 < N_TOK) ? 1.f / lrow[r1] : 0.f;
        float inv2 = (t2 < N_TOK) ? 1.f / lrow[r1 + 8] : 0.f;
#pragma unroll
        for (int ni = 0; ni < 8; ++ni) {
            int col = wn * 64 + ni * 8 + 2 * qc;
            if (t1 < N_TOK)
                *(float2*)(O + (size_t)t1 * DM + head * HD + col) =
                    make_float2(acc_o[ni][0] * inv1, acc_o[ni][1] * inv1);
            if (t2 < N_TOK)
                *(float2*)(O + (size_t)t2 * DM + head * HD + col) =
                    make_float2(acc_o[ni][2] * inv2, acc_o[ni][3] * inv2);
        }
    }
}

// ---------------------------------------------------------------------------
extern "C" void kernel_launch(void* const* d_in, const int* in_sizes, int n_in,
                              void* d_out, int out_size)
{
    const float* x  = (const float*)d_in[0];
    const float* Wq = (const float*)d_in[1];
    const float* bq = (const float*)d_in[2];
    const float* Wk = (const float*)d_in[3];
    const float* bk = (const float*)d_in[4];
    const float* Wv = (const float*)d_in[5];
    const float* bv = (const float*)d_in[6];
    const float* Wo = (const float*)d_in[7];
    const float* bo = (const float*)d_in[8];
    const float* qs = (const float*)d_in[9];
    const float* ks = (const float*)d_in[10];
    const float* ft = (const float*)d_in[11];
    const float* fh = (const float*)d_in[12];
    const float* fw = (const float*)d_in[13];
    float* out = (float*)d_out;

    float *pq, *pk, *pv, *po;
    cudaGetSymbolAddress((void**)&pq, g_q);
    cudaGetSymbolAddress((void**)&pk, g_k);
    cudaGetSymbolAddress((void**)&pv, g_v);
    cudaGetSymbolAddress((void**)&po, g_o);

    cudaFuncSetAttribute(attn_kernel,
                         cudaFuncAttributeMaxDynamicSharedMemorySize,
                         ATT_SMEM_BYTES);

    dim3 gg(DM / 128, (N_TOK + 127) / 128);
    gemm_tf32_kernel<<<gg, 256>>>(x, Wq, bq, pq, N_TOK);
    gemm_tf32_kernel<<<gg, 256>>>(x, Wk, bk, pk, N_TOK);
    gemm_tf32_kernel<<<gg, 256>>>(x, Wv, bv, pv, N_TOK);

    rms_rope_kernel<<<N_TOK, 256>>>(pq, pk, qs, ks, ft, fh, fw);

    dim3 ga((N_TOK + 63) / 64, NH);
    attn_kernel<<<ga, 256, ATT_SMEM_BYTES>>>(pq, pk, pv, po);

    gemm_tf32_kernel<<<gg, 256>>>(po, Wo, bo, out, N_TOK);
}

// round 3
// speedup vs baseline: 4.3617x; 1.3318x over previous
#include <cuda_runtime.h>
#include <math.h>

#define N_TOK 2925
#define DM    1536
#define NH    12
#define HD    128
#define ATT_SCALE 0.08838834764831845f   // 1/sqrt(128)

// scratch (allocation-free workaround: __device__ globals)
__device__ float g_q[N_TOK * DM];
__device__ float g_k[N_TOK * DM];
__device__ float g_v[N_TOK * DM];
__device__ float g_o[N_TOK * DM];

// ---------------------------------------------------------------------------
// helpers
// ---------------------------------------------------------------------------
__device__ __forceinline__ unsigned f2tf32(float x) {
    unsigned r;
    asm("cvt.rna.tf32.f32 %0, %1;" : "=r"(r) : "f"(x));
    return r;
}

__device__ __forceinline__ void mma_tf32(float* d, const unsigned* a,
                                         const unsigned* b) {
    asm volatile(
        "mma.sync.aligned.m16n8k8.row.col.f32.tf32.tf32.f32 "
        "{%0,%1,%2,%3}, {%4,%5,%6,%7}, {%8,%9}, {%0,%1,%2,%3};"
        : "+f"(d[0]), "+f"(d[1]), "+f"(d[2]), "+f"(d[3])
        : "r"(a[0]), "r"(a[1]), "r"(a[2]), "r"(a[3]), "r"(b[0]), "r"(b[1]));
}

// ---------------------------------------------------------------------------
// tf32 tensor-core GEMM, double-buffered.
// C[M,1536] = A[M,1536] @ B[1536,1536] + bias
// block tile 128x128, BK=32, 256 threads (8 warps, 4m x 2n), warp tile 32x64
// ---------------------------------------------------------------------------
#define SA_STRIDE 36
#define SB_STRIDE 136
#define A_TILE_F (128 * SA_STRIDE)
#define B_TILE_F (32 * SB_STRIDE)
#define GEMM_SMEM_BYTES ((2 * (A_TILE_F + B_TILE_F)) * 4)
#define NK_ITERS (DM / 32)   // 48

__global__ __launch_bounds__(256) void gemm_tf32_kernel(
    const float* __restrict__ A, const float* __restrict__ B,
    const float* __restrict__ bias, float* __restrict__ C, int M)
{
    extern __shared__ float sm[];
    float* AsBase = sm;                     // [2][A_TILE_F]
    float* BsBase = sm + 2 * A_TILE_F;      // [2][B_TILE_F]

    const int tid  = threadIdx.x;
    const int lane = tid & 31;
    const int warp = tid >> 5;
    const int wm   = warp & 3;
    const int wn   = warp >> 2;
    const int qr   = lane >> 2;
    const int qc   = lane & 3;

    const int row0 = blockIdx.y * 128;
    const int col0 = blockIdx.x * 128;

    // global-load coordinates (per l-slice)
    const int a_r  = tid >> 1;              // reused pattern: idx = tid + l*256
    (void)a_r;

    float acc[2][8][4];
#pragma unroll
    for (int i = 0; i < 2; ++i)
#pragma unroll
        for (int j = 0; j < 8; ++j)
#pragma unroll
            for (int t = 0; t < 4; ++t) acc[i][j][t] = 0.f;

    float4 apf[4], bpf[4];

    // ---- prologue: load tile 0 ----
#pragma unroll
    for (int l = 0; l < 4; ++l) {
        int idx = tid + l * 256;
        int r   = idx >> 3;
        int c4  = (idx & 7) * 4;
        apf[l] = make_float4(0.f, 0.f, 0.f, 0.f);
        if (row0 + r < M)
            apf[l] = *(const float4*)(A + (size_t)(row0 + r) * DM + c4);
        int rb = idx >> 5;
        int cb = (idx & 31) * 4;
        bpf[l] = *(const float4*)(B + (size_t)rb * DM + col0 + cb);
    }
    // store stage 0
    {
        float* As = AsBase;
        float* Bs = BsBase;
#pragma unroll
        for (int l = 0; l < 4; ++l) {
            int idx = tid + l * 256;
            int r   = idx >> 3;
            int c4  = (idx & 7) * 4;
            float* p = &As[r * SA_STRIDE + c4];
            p[0] = __uint_as_float(f2tf32(apf[l].x));
            p[1] = __uint_as_float(f2tf32(apf[l].y));
            p[2] = __uint_as_float(f2tf32(apf[l].z));
            p[3] = __uint_as_float(f2tf32(apf[l].w));
            int rb = idx >> 5;
            int cb = (idx & 31) * 4;
            float* pb = &Bs[rb * SB_STRIDE + cb];
            pb[0] = __uint_as_float(f2tf32(bpf[l].x));
            pb[1] = __uint_as_float(f2tf32(bpf[l].y));
            pb[2] = __uint_as_float(f2tf32(bpf[l].z));
            pb[3] = __uint_as_float(f2tf32(bpf[l].w));
        }
    }
    __syncthreads();

    int st = 0;
    for (int t = 1; t <= NK_ITERS; ++t) {
        const bool has_next = (t < NK_ITERS);
        if (has_next) {
            const int k0 = t * 32;
#pragma unroll
            for (int l = 0; l < 4; ++l) {
                int idx = tid + l * 256;
                int r   = idx >> 3;
                int c4  = (idx & 7) * 4;
                apf[l] = make_float4(0.f, 0.f, 0.f, 0.f);
                if (row0 + r < M)
                    apf[l] = *(const float4*)(A + (size_t)(row0 + r) * DM + k0 + c4);
                int rb = idx >> 5;
                int cb = (idx & 31) * 4;
                bpf[l] = *(const float4*)(B + (size_t)(k0 + rb) * DM + col0 + cb);
            }
        }

        // ---- compute on stage st ----
        {
            const unsigned* Asu = (const unsigned*)(AsBase + st * A_TILE_F);
            const unsigned* Bsu = (const unsigned*)(BsBase + st * B_TILE_F);
#pragma unroll
            for (int ks = 0; ks < 4; ++ks) {
                const int kb = ks * 8;
                unsigned a[2][4];
#pragma unroll
                for (int mi = 0; mi < 2; ++mi) {
                    int r = wm * 32 + mi * 16 + qr;
                    a[mi][0] = Asu[r * SA_STRIDE + kb + qc];
                    a[mi][1] = Asu[(r + 8) * SA_STRIDE + kb + qc];
                    a[mi][2] = Asu[r * SA_STRIDE + kb + qc + 4];
                    a[mi][3] = Asu[(r + 8) * SA_STRIDE + kb + qc + 4];
                }
                unsigned b[8][2];
#pragma unroll
                for (int ni = 0; ni < 8; ++ni) {
                    int col = wn * 64 + ni * 8 + qr;
                    b[ni][0] = Bsu[(kb + qc) * SB_STRIDE + col];
                    b[ni][1] = Bsu[(kb + qc + 4) * SB_STRIDE + col];
                }
#pragma unroll
                for (int mi = 0; mi < 2; ++mi)
#pragma unroll
                    for (int ni = 0; ni < 8; ++ni)
                        mma_tf32(acc[mi][ni], a[mi], b[ni]);
            }
        }

        if (has_next) {
            float* As = AsBase + (st ^ 1) * A_TILE_F;
            float* Bs = BsBase + (st ^ 1) * B_TILE_F;
#pragma unroll
            for (int l = 0; l < 4; ++l) {
                int idx = tid + l * 256;
                int r   = idx >> 3;
                int c4  = (idx & 7) * 4;
                float* p = &As[r * SA_STRIDE + c4];
                p[0] = __uint_as_float(f2tf32(apf[l].x));
                p[1] = __uint_as_float(f2tf32(apf[l].y));
                p[2] = __uint_as_float(f2tf32(apf[l].z));
                p[3] = __uint_as_float(f2tf32(apf[l].w));
                int rb = idx >> 5;
                int cb = (idx & 31) * 4;
                float* pb = &Bs[rb * SB_STRIDE + cb];
                pb[0] = __uint_as_float(f2tf32(bpf[l].x));
                pb[1] = __uint_as_float(f2tf32(bpf[l].y));
                pb[2] = __uint_as_float(f2tf32(bpf[l].z));
                pb[3] = __uint_as_float(f2tf32(bpf[l].w));
            }
            __syncthreads();
        }
        st ^= 1;
    }

    // store C
#pragma unroll
    for (int mi = 0; mi < 2; ++mi) {
#pragma unroll
        for (int ni = 0; ni < 8; ++ni) {
            int col = col0 + wn * 64 + ni * 8 + 2 * qc;
            int r1  = row0 + wm * 32 + mi * 16 + qr;
            int r2  = r1 + 8;
            if (r1 < M) {
                float2 v = make_float2(acc[mi][ni][0] + bias[col],
                                       acc[mi][ni][1] + bias[col + 1]);
                *(float2*)(C + (size_t)r1 * DM + col) = v;
            }
            if (r2 < M) {
                float2 v = make_float2(acc[mi][ni][2] + bias[col],
                                       acc[mi][ni][3] + bias[col + 1]);
                *(float2*)(C + (size_t)r2 * DM + col) = v;
            }
        }
    }
}

// ---------------------------------------------------------------------------
// Fused RMSNorm + 3D RoPE for Q and K. One block per token. (unchanged)
// ---------------------------------------------------------------------------
__global__ __launch_bounds__(256) void rms_rope_kernel(
    float* __restrict__ q, float* __restrict__ k,
    const float* __restrict__ qscale, const float* __restrict__ kscale,
    const float* __restrict__ ft, const float* __restrict__ fh,
    const float* __restrict__ fw)
{
    const int n   = blockIdx.x;
    const int tid = threadIdx.x;
    float* qr = q + (size_t)n * DM;
    float* kr = k + (size_t)n * DM;

    float sq = 0.f, sk = 0.f;
    for (int i = tid; i < DM; i += 256) {
        float a = qr[i]; sq += a * a;
        float b = kr[i]; sk += b * b;
    }
#pragma unroll
    for (int o = 16; o; o >>= 1) {
        sq += __shfl_xor_sync(0xffffffffu, sq, o);
        sk += __shfl_xor_sync(0xffffffffu, sk, o);
    }
    __shared__ float aq[8], ak[8];
    __shared__ float s_rq, s_rk;
    if ((tid & 31) == 0) { aq[tid >> 5] = sq; ak[tid >> 5] = sk; }
    __syncthreads();
    if (tid == 0) {
        float a = 0.f, b = 0.f;
#pragma unroll
        for (int i = 0; i < 8; ++i) { a += aq[i]; b += ak[i]; }
        s_rq = rsqrtf(a / (float)DM + 1e-6f);
        s_rk = rsqrtf(b / (float)DM + 1e-6f);
    }
    __syncthreads();
    const float rq = s_rq, rk = s_rk;

    const int wi = n % 15;
    const int hi = (n / 15) % 15;
    const int fi = n / 225;

    for (int pi = tid; pi < NH * (HD / 2); pi += 256) {
        const int head = pi >> 6;
        const int p    = pi & 63;
        float c, s;
        if (p < 22) {
            c = ft[(fi * 22 + p) * 2];
            s = ft[(fi * 22 + p) * 2 + 1];
        } else if (p < 43) {
            int pp = p - 22;
            c = fh[(hi * 21 + pp) * 2];
            s = fh[(hi * 21 + pp) * 2 + 1];
        } else {
            int pp = p - 43;
            c = fw[(wi * 21 + pp) * 2];
            s = fw[(wi * 21 + pp) * 2 + 1];
        }
        const int e0 = head * HD + 2 * p;
        const int e1 = e0 + 1;
        float x0 = qr[e0] * rq * qscale[e0];
        float x1 = qr[e1] * rq * qscale[e1];
        qr[e0] = x0 * c - x1 * s;
        qr[e1] = x0 * s + x1 * c;
        float y0 = kr[e0] * rk * kscale[e0];
        float y1 = kr[e1] * rk * kscale[e1];
        kr[e0] = y0 * c - y1 * s;
        kr[e1] = y0 * s + y1 * c;
    }
}

// ---------------------------------------------------------------------------
// Flash attention, tf32 tensor cores, no-max softmax (scores bounded ~11
// because q,k are RMS-normalized), Q tile 128, KV tile 64, 512 threads.
// Warp grid 4m x 4n. S warp tile 32x16; PV warp tile 32x32.
// Row sums accumulate in registers across tiles; one atomicAdd at end.
// KV register prefetch overlaps next tile's LDG with PV compute.
// ---------------------------------------------------------------------------
#define BQ 128
#define BKV 64
#define Q_STRIDE 132
#define K_STRIDE 132
#define V_STRIDE 136
#define S_STRIDE 68
#define ATT_SMEM_FLOATS (BQ*Q_STRIDE + BKV*K_STRIDE + BKV*V_STRIDE + BQ*S_STRIDE + BQ)
#define ATT_SMEM_BYTES  (ATT_SMEM_FLOATS * 4)
#define NKT ((N_TOK + BKV - 1) / BKV)   // 46

__global__ __launch_bounds__(512) void attn_kernel(
    const float* __restrict__ Q, const float* __restrict__ Kg,
    const float* __restrict__ Vg, float* __restrict__ O)
{
    extern __shared__ float smf[];
    float* Qs   = smf;                        // 128 x 132 (tf32, pre-scaled)
    float* Ks   = Qs + BQ * Q_STRIDE;         // 64 x 132
    float* Vs   = Ks + BKV * K_STRIDE;        // 64 x 136
    float* Ss   = Vs + BKV * V_STRIDE;        // 128 x 68 (P, tf32)
    float* lrow = Ss + BQ * S_STRIDE;         // 128
    const unsigned* Qsu = (const unsigned*)Qs;
    const unsigned* Ksu = (const unsigned*)Ks;
    const unsigned* Vsu = (const unsigned*)Vs;
    const unsigned* Ssu = (const unsigned*)Ss;

    const int tid  = threadIdx.x;
    const int lane = tid & 31;
    const int warp = tid >> 5;
    const int wm   = warp & 3;     // m group: 32 rows
    const int wn   = warp >> 2;    // n group: 16 cols (S) / 32 cols (PV)
    const int qr   = lane >> 2;
    const int qc   = lane & 3;
    const int head = blockIdx.y;
    const int q0   = blockIdx.x * BQ;

    // load Q tile (128x128), scale folded in, tf32-rounded
#pragma unroll
    for (int l = 0; l < 8; ++l) {
        int idx = tid + l * 512;           // 0..4095 float4
        int r   = idx >> 5;                // 0..127
        int c4  = (idx & 31) * 4;
        int t   = q0 + r;
        float4 v = make_float4(0.f, 0.f, 0.f, 0.f);
        if (t < N_TOK)
            v = *(const float4*)(Q + (size_t)t * DM + head * HD + c4);
        float* p = &Qs[r * Q_STRIDE + c4];
        p[0] = __uint_as_float(f2tf32(v.x * ATT_SCALE));
        p[1] = __uint_as_float(f2tf32(v.y * ATT_SCALE));
        p[2] = __uint_as_float(f2tf32(v.z * ATT_SCALE));
        p[3] = __uint_as_float(f2tf32(v.w * ATT_SCALE));
    }
    if (tid < BQ) lrow[tid] = 0.f;

    float acc_o[2][4][4];
#pragma unroll
    for (int mi = 0; mi < 2; ++mi)
#pragma unroll
        for (int ni = 0; ni < 4; ++ni)
#pragma unroll
            for (int t = 0; t < 4; ++t) acc_o[mi][ni][t] = 0.f;
    float acc_l[2][2] = {{0.f, 0.f}, {0.f, 0.f}};

    float4 kpf[4], vpf[4];
    // prologue: load KV tile 0 and store (no sync needed yet vs Q-load sync below)
#pragma unroll
    for (int l = 0; l < 4; ++l) {
        int idx = tid + l * 512;           // 0..2047 float4
        int r   = idx >> 5;                // 0..63
        int c4  = (idx & 31) * 4;
        kpf[l] = *(const float4*)(Kg + (size_t)r * DM + head * HD + c4);
        vpf[l] = *(const float4*)(Vg + (size_t)r * DM + head * HD + c4);
    }
#pragma unroll
    for (int l = 0; l < 4; ++l) {
        int idx = tid + l * 512;
        int r   = idx >> 5;
        int c4  = (idx & 31) * 4;
        float* pk = &Ks[r * K_STRIDE + c4];
        pk[0] = __uint_as_float(f2tf32(kpf[l].x));
        pk[1] = __uint_as_float(f2tf32(kpf[l].y));
        pk[2] = __uint_as_float(f2tf32(kpf[l].z));
        pk[3] = __uint_as_float(f2tf32(kpf[l].w));
        float* pv = &Vs[r * V_STRIDE + c4];
        pv[0] = __uint_as_float(f2tf32(vpf[l].x));
        pv[1] = __uint_as_float(f2tf32(vpf[l].y));
        pv[2] = __uint_as_float(f2tf32(vpf[l].z));
        pv[3] = __uint_as_float(f2tf32(vpf[l].w));
    }

    for (int kt = 0; kt < NKT; ++kt) {
        __syncthreads();   // (a) KV tile in smem; prev P consumed
        const int kv0 = kt * BKV;
        const int rem = N_TOK - kv0;   // >= 64 except last tile (45)

        // ---- S = Qs @ Ks^T ----
        float acc_s[2][2][4];
#pragma unroll
        for (int mi = 0; mi < 2; ++mi)
#pragma unroll
            for (int ni = 0; ni < 2; ++ni)
#pragma unroll
                for (int t = 0; t < 4; ++t) acc_s[mi][ni][t] = 0.f;

#pragma unroll
        for (int ks = 0; ks < 16; ++ks) {
            const int kb = ks * 8;
            unsigned a[2][4];
#pragma unroll
            for (int mi = 0; mi < 2; ++mi) {
                int r = wm * 32 + mi * 16 + qr;
                a[mi][0] = Qsu[r * Q_STRIDE + kb + qc];
                a[mi][1] = Qsu[(r + 8) * Q_STRIDE + kb + qc];
                a[mi][2] = Qsu[r * Q_STRIDE + kb + qc + 4];
                a[mi][3] = Qsu[(r + 8) * Q_STRIDE + kb + qc + 4];
            }
            unsigned b[2][2];
#pragma unroll
            for (int ni = 0; ni < 2; ++ni) {
                int n = wn * 16 + ni * 8 + qr;
                b[ni][0] = Ksu[n * K_STRIDE + kb + qc];
                b[ni][1] = Ksu[n * K_STRIDE + kb + qc + 4];
            }
#pragma unroll
            for (int mi = 0; mi < 2; ++mi)
#pragma unroll
                for (int ni = 0; ni < 2; ++ni)
                    mma_tf32(acc_s[mi][ni], a[mi], b[ni]);
        }

        // ---- exp (no max shift), row-sum accumulate, store P (tf32) ----
#pragma unroll
        for (int mi = 0; mi < 2; ++mi) {
#pragma unroll
            for (int ni = 0; ni < 2; ++ni) {
                int col = wn * 16 + ni * 8 + 2 * qc;
                float e0 = __expf(acc_s[mi][ni][0]);
                float e1 = __expf(acc_s[mi][ni][1]);
                float e2 = __expf(acc_s[mi][ni][2]);
                float e3 = __expf(acc_s[mi][ni][3]);
                if (rem < BKV) {
                    if (col     >= rem) { e0 = 0.f; e2 = 0.f; }
                    if (col + 1 >= rem) { e1 = 0.f; e3 = 0.f; }
                }
                acc_l[mi][0] += e0 + e1;
                acc_l[mi][1] += e2 + e3;
                int r1 = wm * 32 + mi * 16 + qr;
                *(float2*)(&Ss[r1 * S_STRIDE + col]) =
                    make_float2(__uint_as_float(f2tf32(e0)),
                                __uint_as_float(f2tf32(e1)));
                *(float2*)(&Ss[(r1 + 8) * S_STRIDE + col]) =
                    make_float2(__uint_as_float(f2tf32(e2)),
                                __uint_as_float(f2tf32(e3)));
            }
        }

        // prefetch next KV tile into registers (overlaps with PV below)
        const bool has_next = (kt + 1 < NKT);
        if (has_next) {
            const int nkv0 = kv0 + BKV;
#pragma unroll
            for (int l = 0; l < 4; ++l) {
                int idx = tid + l * 512;
                int r   = idx >> 5;
                int c4  = (idx & 31) * 4;
                int t   = nkv0 + r;
                kpf[l] = make_float4(0.f, 0.f, 0.f, 0.f);
                vpf[l] = make_float4(0.f, 0.f, 0.f, 0.f);
                if (t < N_TOK) {
                    kpf[l] = *(const float4*)(Kg + (size_t)t * DM + head * HD + c4);
                    vpf[l] = *(const float4*)(Vg + (size_t)t * DM + head * HD + c4);
                }
            }
        }

        __syncthreads();   // (b) P visible to all warps

        // ---- O += P @ V ----
#pragma unroll
        for (int ks = 0; ks < 8; ++ks) {
            const int kb = ks * 8;
            unsigned a[2][4];
#pragma unroll
            for (int mi = 0; mi < 2; ++mi) {
                int r = wm * 32 + mi * 16 + qr;
                a[mi][0] = Ssu[r * S_STRIDE + kb + qc];
                a[mi][1] = Ssu[(r + 8) * S_STRIDE + kb + qc];
                a[mi][2] = Ssu[r * S_STRIDE + kb + qc + 4];
                a[mi][3] = Ssu[(r + 8) * S_STRIDE + kb + qc + 4];
            }
            unsigned b[4][2];
#pragma unroll
            for (int ni = 0; ni < 4; ++ni) {
                int d = wn * 32 + ni * 8 + qr;
                b[ni][0] = Vsu[(kb + qc) * V_STRIDE + d];
                b[ni][1] = Vsu[(kb + qc + 4) * V_STRIDE + d];
            }
#pragma unroll
            for (int mi = 0; mi < 2; ++mi)
#pragma unroll
                for (int ni = 0; ni < 4; ++ni)
                    mma_tf32(acc_o[mi][ni], a[mi], b[ni]);
        }

        if (has_next) {
            __syncthreads();   // (c) all reads of Ks/Vs done
#pragma unroll
            for (int l = 0; l < 4; ++l) {
                int idx = tid + l * 512;
                int r   = idx >> 5;
                int c4  = (idx & 31) * 4;
                float* pk = &Ks[r * K_STRIDE + c4];
                pk[0] = __uint_as_float(f2tf32(kpf[l].x));
                pk[1] = __uint_as_float(f2tf32(kpf[l].y));
                pk[2] = __uint_as_float(f2tf32(kpf[l].z));
                pk[3] = __uint_as_float(f2tf32(kpf[l].w));
                float* pv = &Vs[r * V_STRIDE + c4];
                pv[0] = __uint_as_float(f2tf32(vpf[l].x));
                pv[1] = __uint_as_float(f2tf32(vpf[l].y));
                pv[2] = __uint_as_float(f2tf32(vpf[l].z));
                pv[3] = __uint_as_float(f2tf32(vpf[l].w));
            }
        }
    }

    // reduce row sums: over qc lanes, then across the 4 wn warps via shared
#pragma unroll
    for (int mi = 0; mi < 2; ++mi) {
#pragma unroll
        for (int h = 0; h < 2; ++h) {
            float v = acc_l[mi][h];
            v += __shfl_xor_sync(0xffffffffu, v, 1);
            v += __shfl_xor_sync(0xffffffffu, v, 2);
            if (qc == 0)
                atomicAdd(&lrow[wm * 32 + mi * 16 + qr + 8 * h], v);
        }
    }
    __syncthreads();

    // write O = acc / l
#pragma unroll
    for (int mi = 0; mi < 2; ++mi) {
        int r1 = wm * 32 + mi * 16 + qr;
        int t1 = q0 + r1, t2 = t1 + 8;
        float inv1 = (t1 < N_TOK) ? 1.f / lrow[r1] : 0.f;
        float inv2 = (t2 < N_TOK) ? 1.f / lrow[r1 + 8] : 0.f;
#pragma unroll
        for (int ni = 0; ni < 4; ++ni) {
            int col = wn * 32 + ni * 8 + 2 * qc;
            if (t1 < N_TOK)
                *(float2*)(O + (size_t)t1 * DM + head * HD + col) =
                    make_float2(acc_o[mi][ni][0] * inv1, acc_o[mi][ni][1] * inv1);
            if (t2 < N_TOK)
                *(float2*)(O + (size_t)t2 * DM + head * HD + col) =
                    make_float2(acc_o[mi][ni][2] * inv2, acc_o[mi][ni][3] * inv2);
        }
    }
}

// ---------------------------------------------------------------------------
extern "C" void kernel_launch(void* const* d_in, const int* in_sizes, int n_in,
                              void* d_out, int out_size)
{
    const float* x  = (const float*)d_in[0];
    const float* Wq = (const float*)d_in[1];
    const float* bq = (const float*)d_in[2];
    const float* Wk = (const float*)d_in[3];
    const float* bk = (const float*)d_in[4];
    const float* Wv = (const float*)d_in[5];
    const float* bv = (const float*)d_in[6];
    const float* Wo = (const float*)d_in[7];
    const float* bo = (const float*)d_in[8];
    const float* qs = (const float*)d_in[9];
    const float* ks = (const float*)d_in[10];
    const float* ft = (const float*)d_in[11];
    const float* fh = (const float*)d_in[12];
    const float* fw = (const float*)d_in[13];
    float* out = (float*)d_out;

    float *pq, *pk, *pv, *po;
    cudaGetSymbolAddress((void**)&pq, g_q);
    cudaGetSymbolAddress((void**)&pk, g_k);
    cudaGetSymbolAddress((void**)&pv, g_v);
    cudaGetSymbolAddress((void**)&po, g_o);

    cudaFuncSetAttribute(gemm_tf32_kernel,
                         cudaFuncAttributeMaxDynamicSharedMemorySize,
                         GEMM_SMEM_BYTES);
    cudaFuncSetAttribute(attn_kernel,
                         cudaFuncAttributeMaxDynamicSharedMemorySize,
                         ATT_SMEM_BYTES);

    dim3 gg(DM / 128, (N_TOK + 127) / 128);
    gemm_tf32_kernel<<<gg, 256, GEMM_SMEM_BYTES>>>(x, Wq, bq, pq, N_TOK);
    gemm_tf32_kernel<<<gg, 256, GEMM_SMEM_BYTES>>>(x, Wk, bk, pk, N_TOK);
    gemm_tf32_kernel<<<gg, 256, GEMM_SMEM_BYTES>>>(x, Wv, bv, pv, N_TOK);

    rms_rope_kernel<<<N_TOK, 256>>>(pq, pk, qs, ks, ft, fh, fw);

    dim3 ga((N_TOK + BQ - 1) / BQ, NH);
    attn_kernel<<<ga, 512, ATT_SMEM_BYTES>>>(pq, pk, pv, po);

    gemm_tf32_kernel<<<gg, 256, GEMM_SMEM_BYTES>>>(po, Wo, bo, out, N_TOK);
}

// round 4
// speedup vs baseline: 8.4612x; 1.9399x over previous
#include <cuda_runtime.h>
#include <cuda_fp16.h>
#include <math.h>

#define N_TOK 2925
#define DM    1536
#define NH    12
#define HD    128
#define ATT_SCALE 0.08838834764831845f   // 1/sqrt(128)
#define EXP_SHIFT 4.0f

// scratch (allocation-free workaround: __device__ globals)
__device__ __half g_xh [N_TOK * DM];
__device__ __half g_qh [N_TOK * DM];
__device__ __half g_kh [N_TOK * DM];
__device__ __half g_vh [N_TOK * DM];
__device__ __half g_oh [N_TOK * DM];
__device__ __half g_wqt[DM * DM];
__device__ __half g_wkt[DM * DM];
__device__ __half g_wvt[DM * DM];
__device__ __half g_wot[DM * DM];

// ---------------------------------------------------------------------------
// helpers
// ---------------------------------------------------------------------------
__device__ __forceinline__ unsigned smaddr(const void* p) {
    return (unsigned)__cvta_generic_to_shared(p);
}

__device__ __forceinline__ void ldsm_x4(unsigned& r0, unsigned& r1,
                                        unsigned& r2, unsigned& r3,
                                        unsigned addr) {
    asm volatile("ldmatrix.sync.aligned.m8n8.x4.shared.b16 {%0,%1,%2,%3}, [%4];"
                 : "=r"(r0), "=r"(r1), "=r"(r2), "=r"(r3) : "r"(addr));
}

__device__ __forceinline__ void ldsm_x4_trans(unsigned& r0, unsigned& r1,
                                              unsigned& r2, unsigned& r3,
                                              unsigned addr) {
    asm volatile("ldmatrix.sync.aligned.m8n8.x4.trans.shared.b16 {%0,%1,%2,%3}, [%4];"
                 : "=r"(r0), "=r"(r1), "=r"(r2), "=r"(r3) : "r"(addr));
}

__device__ __forceinline__ void mma_f16(float* d, const unsigned* a,
                                        const unsigned* b) {
    asm volatile(
        "mma.sync.aligned.m16n8k16.row.col.f32.f16.f16.f32 "
        "{%0,%1,%2,%3}, {%4,%5,%6,%7}, {%8,%9}, {%0,%1,%2,%3};"
        : "+f"(d[0]), "+f"(d[1]), "+f"(d[2]), "+f"(d[3])
        : "r"(a[0]), "r"(a[1]), "r"(a[2]), "r"(a[3]), "r"(b[0]), "r"(b[1]));
}

// A-fragment (m16k16) from smem [row][k], stride S halves
__device__ __forceinline__ void ld_afrag(unsigned* a, unsigned base, int R,
                                         int kb, int S, int lane) {
    int grp = lane >> 3, lr = lane & 7;
    int row = R + lr + (grp & 1) * 8;
    int col = kb + (grp >> 1) * 8;
    ldsm_x4(a[0], a[1], a[2], a[3], base + (unsigned)(row * S + col) * 2u);
}

// two B-fragments (n16 x k16) from smem [n][k]: bl = n..n+7, bh = n+8..n+15
__device__ __forceinline__ void ld_bfrag2(unsigned* bl, unsigned* bh,
                                          unsigned base, int NB, int kb,
                                          int S, int lane) {
    int grp = lane >> 3, lr = lane & 7;
    int row = NB + lr + (grp >> 1) * 8;
    int col = kb + (grp & 1) * 8;
    ldsm_x4(bl[0], bl[1], bh[0], bh[1], base + (unsigned)(row * S + col) * 2u);
}

// two B-fragments via transpose from smem [k][n] (V tiles): d = DB..+7, +8..+15
__device__ __forceinline__ void ld_bfrag2_t(unsigned* bl, unsigned* bh,
                                            unsigned base, int DB, int kb,
                                            int S, int lane) {
    int grp = lane >> 3, lr = lane & 7;
    int row = kb + lr + (grp & 1) * 8;
    int col = DB + (grp >> 1) * 8;
    ldsm_x4_trans(bl[0], bl[1], bh[0], bh[1],
                  base + (unsigned)(row * S + col) * 2u);
}

// ---------------------------------------------------------------------------
// conversion kernels
// ---------------------------------------------------------------------------
__global__ __launch_bounds__(256) void convert_x_kernel(
    const float* __restrict__ x, __half* __restrict__ xh, int n4)
{
    int i = blockIdx.x * 256 + threadIdx.x;
    if (i < n4) {
        float4 v = *(const float4*)(x + i * 4);
        *(__half2*)(xh + i * 4)     = __floats2half2_rn(v.x, v.y);
        *(__half2*)(xh + i * 4 + 2) = __floats2half2_rn(v.z, v.w);
    }
}

// W [K][N] f32 -> Wt [N][K] f16
__global__ __launch_bounds__(256) void transpose_w_kernel(
    const float* __restrict__ W, __half* __restrict__ Wt)
{
    __shared__ float t[32][33];
    const int tx = threadIdx.x, ty = threadIdx.y;
    const int n0 = blockIdx.x * 32, k0 = blockIdx.y * 32;
#pragma unroll
    for (int j = 0; j < 32; j += 8)
        t[ty + j][tx] = W[(size_t)(k0 + ty + j) * DM + n0 + tx];
    __syncthreads();
#pragma unroll
    for (int j = 0; j < 32; j += 8)
        Wt[(size_t)(n0 + ty + j) * DM + k0 + tx] = __float2half(t[tx][ty + j]);
}

// ---------------------------------------------------------------------------
// fp16 tensor-core GEMM, double-buffered, ldmatrix fragments.
// C[M,1536] = A[M,1536](f16, k-major) @ Bt[1536,1536](f16, [n][k]) + bias
// block 128x128, BK=32, 256 threads (8 warps 4m x 2n), warp tile 32x64
// ---------------------------------------------------------------------------
#define SA 40                      // halves stride (80 B rows)
#define A_TILE_H (128 * SA)
#define GEMM_SMEM_BYTES (4 * A_TILE_H * 2)   // 2 stages x (A + B)

template <bool HALF_OUT>
__global__ __launch_bounds__(256) void gemm_f16_kernel(
    const __half* __restrict__ A, const __half* __restrict__ Bt,
    const float* __restrict__ bias, void* __restrict__ Cv, int M)
{
    extern __shared__ __half smh[];
    __half* AsB = smh;                    // [2][A_TILE_H]
    __half* BsB = smh + 2 * A_TILE_H;     // [2][A_TILE_H]

    const int tid  = threadIdx.x;
    const int lane = tid & 31;
    const int warp = tid >> 5;
    const int wm   = warp & 3;
    const int wn   = warp >> 2;
    const int qr   = lane >> 2;
    const int qc   = lane & 3;
    const int row0 = blockIdx.y * 128;
    const int col0 = blockIdx.x * 128;

    float acc[2][8][4];
#pragma unroll
    for (int i = 0; i < 2; ++i)
#pragma unroll
        for (int j = 0; j < 8; ++j)
#pragma unroll
            for (int t = 0; t < 4; ++t) acc[i][j][t] = 0.f;

    uint4 apf[2], bpf[2];
    const uint4 z4 = make_uint4(0, 0, 0, 0);

#pragma unroll
    for (int l = 0; l < 2; ++l) {
        int idx = tid + l * 256;
        int r = idx >> 2, c8 = (idx & 3) * 8;
        apf[l] = (row0 + r < M)
                     ? *(const uint4*)(A + (size_t)(row0 + r) * DM + c8) : z4;
        bpf[l] = *(const uint4*)(Bt + (size_t)(col0 + r) * DM + c8);
    }
#pragma unroll
    for (int l = 0; l < 2; ++l) {
        int idx = tid + l * 256;
        int r = idx >> 2, c8 = (idx & 3) * 8;
        *(uint4*)(AsB + r * SA + c8) = apf[l];
        *(uint4*)(BsB + r * SA + c8) = bpf[l];
    }
    __syncthreads();

    int st = 0;
    const int NK = DM / 32;
    for (int t = 1; t <= NK; ++t) {
        const bool has_next = (t < NK);
        if (has_next) {
            const int k0 = t * 32;
#pragma unroll
            for (int l = 0; l < 2; ++l) {
                int idx = tid + l * 256;
                int r = idx >> 2, c8 = (idx & 3) * 8;
                apf[l] = (row0 + r < M)
                             ? *(const uint4*)(A + (size_t)(row0 + r) * DM + k0 + c8)
                             : z4;
                bpf[l] = *(const uint4*)(Bt + (size_t)(col0 + r) * DM + k0 + c8);
            }
        }

        {
            unsigned abase = smaddr(AsB + st * A_TILE_H);
            unsigned bbase = smaddr(BsB + st * A_TILE_H);
#pragma unroll
            for (int ks = 0; ks < 2; ++ks) {
                const int kb = ks * 16;
                unsigned a[2][4];
#pragma unroll
                for (int mi = 0; mi < 2; ++mi)
                    ld_afrag(a[mi], abase, wm * 32 + mi * 16, kb, SA, lane);
                unsigned b[8][2];
#pragma unroll
                for (int g = 0; g < 4; ++g)
                    ld_bfrag2(b[2 * g], b[2 * g + 1], bbase,
                              wn * 64 + g * 16, kb, SA, lane);
#pragma unroll
                for (int mi = 0; mi < 2; ++mi)
#pragma unroll
                    for (int ni = 0; ni < 8; ++ni)
                        mma_f16(acc[mi][ni], a[mi], b[ni]);
            }
        }

        if (has_next) {
            __half* As = AsB + (st ^ 1) * A_TILE_H;
            __half* Bs = BsB + (st ^ 1) * A_TILE_H;
#pragma unroll
            for (int l = 0; l < 2; ++l) {
                int idx = tid + l * 256;
                int r = idx >> 2, c8 = (idx & 3) * 8;
                *(uint4*)(As + r * SA + c8) = apf[l];
                *(uint4*)(Bs + r * SA + c8) = bpf[l];
            }
            __syncthreads();
        }
        st ^= 1;
    }

    // epilogue
#pragma unroll
    for (int mi = 0; mi < 2; ++mi) {
#pragma unroll
        for (int ni = 0; ni < 8; ++ni) {
            int col = col0 + wn * 64 + ni * 8 + 2 * qc;
            int r1  = row0 + wm * 32 + mi * 16 + qr;
            int r2  = r1 + 8;
            float b0 = bias[col], b1 = bias[col + 1];
            if (HALF_OUT) {
                __half* C = (__half*)Cv;
                if (r1 < M)
                    *(__half2*)(C + (size_t)r1 * DM + col) =
                        __floats2half2_rn(acc[mi][ni][0] + b0, acc[mi][ni][1] + b1);
                if (r2 < M)
                    *(__half2*)(C + (size_t)r2 * DM + col) =
                        __floats2half2_rn(acc[mi][ni][2] + b0, acc[mi][ni][3] + b1);
            } else {
                float* C = (float*)Cv;
                if (r1 < M)
                    *(float2*)(C + (size_t)r1 * DM + col) =
                        make_float2(acc[mi][ni][0] + b0, acc[mi][ni][1] + b1);
                if (r2 < M)
                    *(float2*)(C + (size_t)r2 * DM + col) =
                        make_float2(acc[mi][ni][2] + b0, acc[mi][ni][3] + b1);
            }
        }
    }
}

// ---------------------------------------------------------------------------
// Fused RMSNorm + 3D RoPE on fp16 Q,K (in place). ATT_SCALE folded into Q.
// ---------------------------------------------------------------------------
__global__ __launch_bounds__(256) void rms_rope_kernel(
    __half* __restrict__ q, __half* __restrict__ k,
    const float* __restrict__ qscale, const float* __restrict__ kscale,
    const float* __restrict__ ft, const float* __restrict__ fh,
    const float* __restrict__ fw)
{
    const int n   = blockIdx.x;
    const int tid = threadIdx.x;
    __half2* q2 = (__half2*)(q + (size_t)n * DM);
    __half2* k2 = (__half2*)(k + (size_t)n * DM);

    float sq = 0.f, sk = 0.f;
#pragma unroll
    for (int i = tid; i < DM / 2; i += 256) {
        float2 a = __half22float2(q2[i]); sq += a.x * a.x + a.y * a.y;
        float2 b = __half22float2(k2[i]); sk += b.x * b.x + b.y * b.y;
    }
#pragma unroll
    for (int o = 16; o; o >>= 1) {
        sq += __shfl_xor_sync(0xffffffffu, sq, o);
        sk += __shfl_xor_sync(0xffffffffu, sk, o);
    }
    __shared__ float aq[8], ak[8];
    __shared__ float s_rq, s_rk;
    if ((tid & 31) == 0) { aq[tid >> 5] = sq; ak[tid >> 5] = sk; }
    __syncthreads();
    if (tid == 0) {
        float a = 0.f, b = 0.f;
#pragma unroll
        for (int i = 0; i < 8; ++i) { a += aq[i]; b += ak[i]; }
        s_rq = rsqrtf(a / (float)DM + 1e-6f);
        s_rk = rsqrtf(b / (float)DM + 1e-6f);
    }
    __syncthreads();
    const float rq = s_rq, rk = s_rk;

    const int wi = n % 15;
    const int hi = (n / 15) % 15;
    const int fi = n / 225;

    for (int pi = tid; pi < NH * (HD / 2); pi += 256) {
        const int p = pi & 63;
        float c, s;
        if (p < 22) {
            c = ft[(fi * 22 + p) * 2];
            s = ft[(fi * 22 + p) * 2 + 1];
        } else if (p < 43) {
            int pp = p - 22;
            c = fh[(hi * 21 + pp) * 2];
            s = fh[(hi * 21 + pp) * 2 + 1];
        } else {
            int pp = p - 43;
            c = fw[(wi * 21 + pp) * 2];
            s = fw[(wi * 21 + pp) * 2 + 1];
        }
        float2 xv = __half22float2(q2[pi]);
        float x0 = xv.x * rq * qscale[2 * pi];
        float x1 = xv.y * rq * qscale[2 * pi + 1];
        q2[pi] = __floats2half2_rn((x0 * c - x1 * s) * ATT_SCALE,
                                   (x0 * s + x1 * c) * ATT_SCALE);
        float2 yv = __half22float2(k2[pi]);
        float y0 = yv.x * rk * kscale[2 * pi];
        float y1 = yv.y * rk * kscale[2 * pi + 1];
        k2[pi] = __floats2half2_rn(y0 * c - y1 * s, y0 * s + y1 * c);
    }
}

// ---------------------------------------------------------------------------
// Flash attention, fp16 mma, no-max softmax with fixed EXP_SHIFT.
// Q tile 128, KV tile 64, 512 threads (16 warps 4m x 4n).
// ---------------------------------------------------------------------------
#define BQ 128
#define BKV 64
#define SQK 136    // Q/K/V smem stride (halves)
#define SP  72     // P smem stride (halves)
#define ATT_SMEM_BYTES ((BQ*SQK + BKV*SQK + BKV*SQK + BQ*SP) * 2 + BQ * 4)
#define NKT ((N_TOK + BKV - 1) / BKV)   // 46

__global__ __launch_bounds__(512) void attn_kernel(
    const __half* __restrict__ Q, const __half* __restrict__ Kg,
    const __half* __restrict__ Vg, __half* __restrict__ O)
{
    extern __shared__ __half smh[];
    __half* Qs = smh;                     // 128 x 136
    __half* Ks = Qs + BQ * SQK;           // 64 x 136
    __half* Vs = Ks + BKV * SQK;          // 64 x 136
    __half* Ps = Vs + BKV * SQK;          // 128 x 72
    float* lrow = (float*)(Ps + BQ * SP); // 128

    const int tid  = threadIdx.x;
    const int lane = tid & 31;
    const int warp = tid >> 5;
    const int wm   = warp & 3;
    const int wn   = warp >> 2;
    const int qr   = lane >> 2;
    const int qc   = lane & 3;
    const int head = blockIdx.y;
    const int q0   = blockIdx.x * BQ;

    const unsigned qbase = smaddr(Qs);
    const unsigned kbase = smaddr(Ks);
    const unsigned vbase = smaddr(Vs);
    const unsigned pbase = smaddr(Ps);
    const uint4 z4 = make_uint4(0, 0, 0, 0);

    // load Q tile (128 x 128 halves)
#pragma unroll
    for (int l = 0; l < 4; ++l) {
        int idx = tid + l * 512;
        int r = idx >> 4, c8 = (idx & 15) * 8;
        int t = q0 + r;
        uint4 v = (t < N_TOK)
                      ? *(const uint4*)(Q + (size_t)t * DM + head * HD + c8) : z4;
        *(uint4*)(Qs + r * SQK + c8) = v;
    }
    if (tid < BQ) lrow[tid] = 0.f;

    float acc_o[2][4][4];
#pragma unroll
    for (int mi = 0; mi < 2; ++mi)
#pragma unroll
        for (int ni = 0; ni < 4; ++ni)
#pragma unroll
            for (int t = 0; t < 4; ++t) acc_o[mi][ni][t] = 0.f;
    float acc_l[2][2] = {{0.f, 0.f}, {0.f, 0.f}};

    uint4 kpf[2], vpf[2];
#pragma unroll
    for (int l = 0; l < 2; ++l) {
        int idx = tid + l * 512;
        int r = idx >> 4, c8 = (idx & 15) * 8;
        kpf[l] = *(const uint4*)(Kg + (size_t)r * DM + head * HD + c8);
        vpf[l] = *(const uint4*)(Vg + (size_t)r * DM + head * HD + c8);
    }
#pragma unroll
    for (int l = 0; l < 2; ++l) {
        int idx = tid + l * 512;
        int r = idx >> 4, c8 = (idx & 15) * 8;
        *(uint4*)(Ks + r * SQK + c8) = kpf[l];
        *(uint4*)(Vs + r * SQK + c8) = vpf[l];
    }

    for (int kt = 0; kt < NKT; ++kt) {
        __syncthreads();                  // KV tile ready; prev P consumed
        const int kv0 = kt * BKV;
        const int rem = N_TOK - kv0;

        // ---- S = Q @ K^T ----
        float acc_s[2][2][4];
#pragma unroll
        for (int mi = 0; mi < 2; ++mi)
#pragma unroll
            for (int ni = 0; ni < 2; ++ni)
#pragma unroll
                for (int t = 0; t < 4; ++t) acc_s[mi][ni][t] = 0.f;

#pragma unroll
        for (int ks = 0; ks < 8; ++ks) {
            const int kb = ks * 16;
            unsigned a[2][4];
#pragma unroll
            for (int mi = 0; mi < 2; ++mi)
                ld_afrag(a[mi], qbase, wm * 32 + mi * 16, kb, SQK, lane);
            unsigned b[2][2];
            ld_bfrag2(b[0], b[1], kbase, wn * 16, kb, SQK, lane);
#pragma unroll
            for (int mi = 0; mi < 2; ++mi)
#pragma unroll
                for (int ni = 0; ni < 2; ++ni)
                    mma_f16(acc_s[mi][ni], a[mi], b[ni]);
        }

        // ---- exp(s - SHIFT), mask, row-sum accumulate, store P fp16 ----
#pragma unroll
        for (int mi = 0; mi < 2; ++mi) {
#pragma unroll
            for (int ni = 0; ni < 2; ++ni) {
                int col = wn * 16 + ni * 8 + 2 * qc;
                float e0 = __expf(acc_s[mi][ni][0] - EXP_SHIFT);
                float e1 = __expf(acc_s[mi][ni][1] - EXP_SHIFT);
                float e2 = __expf(acc_s[mi][ni][2] - EXP_SHIFT);
                float e3 = __expf(acc_s[mi][ni][3] - EXP_SHIFT);
                if (rem < BKV) {
                    if (col     >= rem) { e0 = 0.f; e2 = 0.f; }
                    if (col + 1 >= rem) { e1 = 0.f; e3 = 0.f; }
                }
                acc_l[mi][0] += e0 + e1;
                acc_l[mi][1] += e2 + e3;
                int r1 = wm * 32 + mi * 16 + qr;
                *(__half2*)(Ps + r1 * SP + col)       = __floats2half2_rn(e0, e1);
                *(__half2*)(Ps + (r1 + 8) * SP + col) = __floats2half2_rn(e2, e3);
            }
        }

        // prefetch next KV tile
        const bool has_next = (kt + 1 < NKT);
        if (has_next) {
            const int nkv0 = kv0 + BKV;
#pragma unroll
            for (int l = 0; l < 2; ++l) {
                int idx = tid + l * 512;
                int r = idx >> 4, c8 = (idx & 15) * 8;
                int t = nkv0 + r;
                kpf[l] = z4; vpf[l] = z4;
                if (t < N_TOK) {
                    kpf[l] = *(const uint4*)(Kg + (size_t)t * DM + head * HD + c8);
                    vpf[l] = *(const uint4*)(Vg + (size_t)t * DM + head * HD + c8);
                }
            }
        }

        __syncthreads();                  // P visible

        // ---- O += P @ V ----
#pragma unroll
        for (int ks = 0; ks < 4; ++ks) {
            const int kb = ks * 16;
            unsigned a[2][4];
#pragma unroll
            for (int mi = 0; mi < 2; ++mi)
                ld_afrag(a[mi], pbase, wm * 32 + mi * 16, kb, SP, lane);
            unsigned b[4][2];
            ld_bfrag2_t(b[0], b[1], vbase, wn * 32,      kb, SQK, lane);
            ld_bfrag2_t(b[2], b[3], vbase, wn * 32 + 16, kb, SQK, lane);
#pragma unroll
            for (int mi = 0; mi < 2; ++mi)
#pragma unroll
                for (int ni = 0; ni < 4; ++ni)
                    mma_f16(acc_o[mi][ni], a[mi], b[ni]);
        }

        if (has_next) {
            __syncthreads();              // KV reads done
#pragma unroll
            for (int l = 0; l < 2; ++l) {
                int idx = tid + l * 512;
                int r = idx >> 4, c8 = (idx & 15) * 8;
                *(uint4*)(Ks + r * SQK + c8) = kpf[l];
                *(uint4*)(Vs + r * SQK + c8) = vpf[l];
            }
        }
    }

    // reduce row sums
#pragma unroll
    for (int mi = 0; mi < 2; ++mi) {
#pragma unroll
        for (int h = 0; h < 2; ++h) {
            float v = acc_l[mi][h];
            v += __shfl_xor_sync(0xffffffffu, v, 1);
            v += __shfl_xor_sync(0xffffffffu, v, 2);
            if (qc == 0)
                atomicAdd(&lrow[wm * 32 + mi * 16 + qr + 8 * h], v);
        }
    }
    __syncthreads();

    // write O (fp16) = acc / l
#pragma unroll
    for (int mi = 0; mi < 2; ++mi) {
        int r1 = wm * 32 + mi * 16 + qr;
        int t1 = q0 + r1, t2 = t1 + 8;
        float inv1 = (t1 < N_TOK) ? 1.f / lrow[r1] : 0.f;
        float inv2 = (t2 < N_TOK) ? 1.f / lrow[r1 + 8] : 0.f;
#pragma unroll
        for (int ni = 0; ni < 4; ++ni) {
            int col = wn * 32 + ni * 8 + 2 * qc;
            if (t1 < N_TOK)
                *(__half2*)(O + (size_t)t1 * DM + head * HD + col) =
                    __floats2half2_rn(acc_o[mi][ni][0] * inv1,
                                      acc_o[mi][ni][1] * inv1);
            if (t2 < N_TOK)
                *(__half2*)(O + (size_t)t2 * DM + head * HD + col) =
                    __floats2half2_rn(acc_o[mi][ni][2] * inv2,
                                      acc_o[mi][ni][3] * inv2);
        }
    }
}

// ---------------------------------------------------------------------------
extern "C" void kernel_launch(void* const* d_in, const int* in_sizes, int n_in,
                              void* d_out, int out_size)
{
    const float* x  = (const float*)d_in[0];
    const float* Wq = (const float*)d_in[1];
    const float* bq = (const float*)d_in[2];
    const float* Wk = (const float*)d_in[3];
    const float* bk = (const float*)d_in[4];
    const float* Wv = (const float*)d_in[5];
    const float* bv = (const float*)d_in[6];
    const float* Wo = (const float*)d_in[7];
    const float* bo = (const float*)d_in[8];
    const float* qs = (const float*)d_in[9];
    const float* ks = (const float*)d_in[10];
    const float* ft = (const float*)d_in[11];
    const float* fh = (const float*)d_in[12];
    const float* fw = (const float*)d_in[13];
    float* out = (float*)d_out;

    __half *xh, *qh, *kh, *vh, *oh, *wqt, *wkt, *wvt, *wot;
    cudaGetSymbolAddress((void**)&xh, g_xh);
    cudaGetSymbolAddress((void**)&qh, g_qh);
    cudaGetSymbolAddress((void**)&kh, g_kh);
    cudaGetSymbolAddress((void**)&vh, g_vh);
    cudaGetSymbolAddress((void**)&oh, g_oh);
    cudaGetSymbolAddress((void**)&wqt, g_wqt);
    cudaGetSymbolAddress((void**)&wkt, g_wkt);
    cudaGetSymbolAddress((void**)&wvt, g_wvt);
    cudaGetSymbolAddress((void**)&wot, g_wot);

    cudaFuncSetAttribute(gemm_f16_kernel<true>,
                         cudaFuncAttributeMaxDynamicSharedMemorySize,
                         GEMM_SMEM_BYTES);
    cudaFuncSetAttribute(gemm_f16_kernel<false>,
                         cudaFuncAttributeMaxDynamicSharedMemorySize,
                         GEMM_SMEM_BYTES);
    cudaFuncSetAttribute(attn_kernel,
                         cudaFuncAttributeMaxDynamicSharedMemorySize,
                         ATT_SMEM_BYTES);

    // conversions
    const int n4 = N_TOK * DM / 4;
    convert_x_kernel<<<(n4 + 255) / 256, 256>>>(x, xh, n4);
    dim3 tb(32, 8), tg(DM / 32, DM / 32);
    transpose_w_kernel<<<tg, tb>>>(Wq, wqt);
    transpose_w_kernel<<<tg, tb>>>(Wk, wkt);
    transpose_w_kernel<<<tg, tb>>>(Wv, wvt);
    transpose_w_kernel<<<tg, tb>>>(Wo, wot);

    dim3 gg(DM / 128, (N_TOK + 127) / 128);
    gemm_f16_kernel<true><<<gg, 256, GEMM_SMEM_BYTES>>>(xh, wqt, bq, qh, N_TOK);
    gemm_f16_kernel<true><<<gg, 256, GEMM_SMEM_BYTES>>>(xh, wkt, bk, kh, N_TOK);
    gemm_f16_kernel<true><<<gg, 256, GEMM_SMEM_BYTES>>>(xh, wvt, bv, vh, N_TOK);

    rms_rope_kernel<<<N_TOK, 256>>>(qh, kh, qs, ks, ft, fh, fw);

    dim3 ga((N_TOK + BQ - 1) / BQ, NH);
    attn_kernel<<<ga, 512, ATT_SMEM_BYTES>>>(qh, kh, vh, oh);

    gemm_f16_kernel<false><<<gg, 256, GEMM_SMEM_BYTES>>>(oh, wot, bo, out, N_TOK);
}

// round 7
// speedup vs baseline: 9.1267x; 1.0787x over previous
#include <cuda_runtime.h>
#include <cuda_fp16.h>
#include <cstdint>
#include <math.h>

#define N_TOK 2925
#define DM    1536
#define NH    12
#define HD    128
#define ATT_SCALE 0.08838834764831845f   // 1/sqrt(128)
#define EXP_SHIFT 4.0f

// scratch (allocation-free workaround: __device__ globals)
__device__ __half g_xh [N_TOK * DM];
__device__ __half g_qh [N_TOK * DM];
__device__ __half g_kh [N_TOK * DM];
__device__ __half g_vh [N_TOK * DM];
__device__ __half g_oh [N_TOK * DM];
__device__ __half g_wqt[DM * DM];
__device__ __half g_wkt[DM * DM];
__device__ __half g_wvt[DM * DM];
__device__ __half g_wot[DM * DM];

// ---------------------------------------------------------------------------
// helpers
// ---------------------------------------------------------------------------
__device__ __forceinline__ unsigned smaddr(const void* p) {
    return (unsigned)__cvta_generic_to_shared(p);
}

__device__ __forceinline__ void ldsm_x4(unsigned& r0, unsigned& r1,
                                        unsigned& r2, unsigned& r3,
                                        unsigned addr) {
    asm volatile("ldmatrix.sync.aligned.m8n8.x4.shared.b16 {%0,%1,%2,%3}, [%4];"
                 : "=r"(r0), "=r"(r1), "=r"(r2), "=r"(r3) : "r"(addr));
}

__device__ __forceinline__ void ldsm_x4_trans(unsigned& r0, unsigned& r1,
                                              unsigned& r2, unsigned& r3,
                                              unsigned addr) {
    asm volatile("ldmatrix.sync.aligned.m8n8.x4.trans.shared.b16 {%0,%1,%2,%3}, [%4];"
                 : "=r"(r0), "=r"(r1), "=r"(r2), "=r"(r3) : "r"(addr));
}

__device__ __forceinline__ void mma_f16(float* d, const unsigned* a,
                                        const unsigned* b) {
    asm volatile(
        "mma.sync.aligned.m16n8k16.row.col.f32.f16.f16.f32 "
        "{%0,%1,%2,%3}, {%4,%5,%6,%7}, {%8,%9}, {%0,%1,%2,%3};"
        : "+f"(d[0]), "+f"(d[1]), "+f"(d[2]), "+f"(d[3])
        : "r"(a[0]), "r"(a[1]), "r"(a[2]), "r"(a[3]), "r"(b[0]), "r"(b[1]));
}

__device__ __forceinline__ void ld_afrag(unsigned* a, unsigned base, int R,
                                         int kb, int S, int lane) {
    int grp = lane >> 3, lr = lane & 7;
    int row = R + lr + (grp & 1) * 8;
    int col = kb + (grp >> 1) * 8;
    ldsm_x4(a[0], a[1], a[2], a[3], base + (unsigned)(row * S + col) * 2u);
}

__device__ __forceinline__ void ld_bfrag2(unsigned* bl, unsigned* bh,
                                          unsigned base, int NB, int kb,
                                          int S, int lane) {
    int grp = lane >> 3, lr = lane & 7;
    int row = NB + lr + (grp >> 1) * 8;
    int col = kb + (grp & 1) * 8;
    ldsm_x4(bl[0], bl[1], bh[0], bh[1], base + (unsigned)(row * S + col) * 2u);
}

__device__ __forceinline__ void ld_bfrag2_t(unsigned* bl, unsigned* bh,
                                            unsigned base, int DB, int kb,
                                            int S, int lane) {
    int grp = lane >> 3, lr = lane & 7;
    int row = kb + lr + (grp & 1) * 8;
    int col = DB + (grp >> 1) * 8;
    ldsm_x4_trans(bl[0], bl[1], bh[0], bh[1],
                  base + (unsigned)(row * S + col) * 2u);
}

__device__ __forceinline__ void cp16(unsigned dst, const void* src,
                                     unsigned bytes) {
    asm volatile("cp.async.cg.shared.global [%0], [%1], 16, %2;"
                 :: "r"(dst), "l"(src), "r"(bytes));
}

// ---------------------------------------------------------------------------
// conversion kernels
// ---------------------------------------------------------------------------
__global__ __launch_bounds__(256) void convert_x_kernel(
    const float* __restrict__ x, __half* __restrict__ xh, int n4)
{
    int i = blockIdx.x * 256 + threadIdx.x;
    if (i < n4) {
        float4 v = *(const float4*)(x + i * 4);
        *(__half2*)(xh + i * 4)     = __floats2half2_rn(v.x, v.y);
        *(__half2*)(xh + i * 4 + 2) = __floats2half2_rn(v.z, v.w);
    }
}

// W [K][N] f32 -> Wt [N][K] f16, 4 weights in one launch (z selects)
__global__ __launch_bounds__(256) void transpose_w4_kernel(
    const float* __restrict__ W0, const float* __restrict__ W1,
    const float* __restrict__ W2, const float* __restrict__ W3,
    __half* __restrict__ T0, __half* __restrict__ T1,
    __half* __restrict__ T2, __half* __restrict__ T3)
{
    const int z = blockIdx.z;
    const float* W = (z == 0) ? W0 : (z == 1) ? W1 : (z == 2) ? W2 : W3;
    __half* Wt     = (z == 0) ? T0 : (z == 1) ? T1 : (z == 2) ? T2 : T3;

    __shared__ float t[32][33];
    const int tx = threadIdx.x, ty = threadIdx.y;
    const int n0 = blockIdx.x * 32, k0 = blockIdx.y * 32;
#pragma unroll
    for (int j = 0; j < 32; j += 8)
        t[ty + j][tx] = W[(size_t)(k0 + ty + j) * DM + n0 + tx];
    __syncthreads();
#pragma unroll
    for (int j = 0; j < 32; j += 8)
        Wt[(size_t)(n0 + ty + j) * DM + k0 + tx] = __float2half(t[tx][ty + j]);
}

// ---------------------------------------------------------------------------
// fp16 tensor-core GEMM (mma.sync), double-buffered, ldmatrix fragments.
// QKV variant: blockIdx.z selects among 3 (Bt, bias, C) triples.
// ---------------------------------------------------------------------------
#define SA 40                      // halves stride (80 B rows)
#define A_TILE_H (128 * SA)
#define GEMM_SMEM_BYTES (4 * A_TILE_H * 2)   // 2 stages x (A + B)

template <bool HALF_OUT>
__device__ __forceinline__ void gemm_core(
    const __half* __restrict__ A, const __half* __restrict__ Bt,
    const float* __restrict__ bias, void* __restrict__ Cv, int M,
    __half* smh)
{
    __half* AsB = smh;
    __half* BsB = smh + 2 * A_TILE_H;

    const int tid  = threadIdx.x;
    const int lane = tid & 31;
    const int warp = tid >> 5;
    const int wm   = warp & 3;
    const int wn   = warp >> 2;
    const int qr   = lane >> 2;
    const int qc   = lane & 3;
    const int row0 = blockIdx.y * 128;
    const int col0 = blockIdx.x * 128;

    float acc[2][8][4];
#pragma unroll
    for (int i = 0; i < 2; ++i)
#pragma unroll
        for (int j = 0; j < 8; ++j)
#pragma unroll
            for (int t = 0; t < 4; ++t) acc[i][j][t] = 0.f;

    uint4 apf[2], bpf[2];
    const uint4 z4 = make_uint4(0, 0, 0, 0);

#pragma unroll
    for (int l = 0; l < 2; ++l) {
        int idx = tid + l * 256;
        int r = idx >> 2, c8 = (idx & 3) * 8;
        apf[l] = (row0 + r < M)
                     ? *(const uint4*)(A + (size_t)(row0 + r) * DM + c8) : z4;
        bpf[l] = *(const uint4*)(Bt + (size_t)(col0 + r) * DM + c8);
    }
#pragma unroll
    for (int l = 0; l < 2; ++l) {
        int idx = tid + l * 256;
        int r = idx >> 2, c8 = (idx & 3) * 8;
        *(uint4*)(AsB + r * SA + c8) = apf[l];
        *(uint4*)(BsB + r * SA + c8) = bpf[l];
    }
    __syncthreads();

    int st = 0;
    const int NK = DM / 32;
    for (int t = 1; t <= NK; ++t) {
        const bool has_next = (t < NK);
        if (has_next) {
            const int k0 = t * 32;
#pragma unroll
            for (int l = 0; l < 2; ++l) {
                int idx = tid + l * 256;
                int r = idx >> 2, c8 = (idx & 3) * 8;
                apf[l] = (row0 + r < M)
                             ? *(const uint4*)(A + (size_t)(row0 + r) * DM + k0 + c8)
                             : z4;
                bpf[l] = *(const uint4*)(Bt + (size_t)(col0 + r) * DM + k0 + c8);
            }
        }
        {
            unsigned abase = smaddr(AsB + st * A_TILE_H);
            unsigned bbase = smaddr(BsB + st * A_TILE_H);
#pragma unroll
            for (int ks = 0; ks < 2; ++ks) {
                const int kb = ks * 16;
                unsigned a[2][4];
#pragma unroll
                for (int mi = 0; mi < 2; ++mi)
                    ld_afrag(a[mi], abase, wm * 32 + mi * 16, kb, SA, lane);
                unsigned b[8][2];
#pragma unroll
                for (int g = 0; g < 4; ++g)
                    ld_bfrag2(b[2 * g], b[2 * g + 1], bbase,
                              wn * 64 + g * 16, kb, SA, lane);
#pragma unroll
                for (int mi = 0; mi < 2; ++mi)
#pragma unroll
                    for (int ni = 0; ni < 8; ++ni)
                        mma_f16(acc[mi][ni], a[mi], b[ni]);
            }
        }
        if (has_next) {
            __half* As = AsB + (st ^ 1) * A_TILE_H;
            __half* Bs = BsB + (st ^ 1) * A_TILE_H;
#pragma unroll
            for (int l = 0; l < 2; ++l) {
                int idx = tid + l * 256;
                int r = idx >> 2, c8 = (idx & 3) * 8;
                *(uint4*)(As + r * SA + c8) = apf[l];
                *(uint4*)(Bs + r * SA + c8) = bpf[l];
            }
            __syncthreads();
        }
        st ^= 1;
    }

#pragma unroll
    for (int mi = 0; mi < 2; ++mi) {
#pragma unroll
        for (int ni = 0; ni < 8; ++ni) {
            int col = col0 + wn * 64 + ni * 8 + 2 * qc;
            int r1  = row0 + wm * 32 + mi * 16 + qr;
            int r2  = r1 + 8;
            float b0 = bias[col], b1 = bias[col + 1];
            if (HALF_OUT) {
                __half* C = (__half*)Cv;
                if (r1 < M)
                    *(__half2*)(C + (size_t)r1 * DM + col) =
                        __floats2half2_rn(acc[mi][ni][0] + b0, acc[mi][ni][1] + b1);
                if (r2 < M)
                    *(__half2*)(C + (size_t)r2 * DM + col) =
                        __floats2half2_rn(acc[mi][ni][2] + b0, acc[mi][ni][3] + b1);
            } else {
                float* C = (float*)Cv;
                if (r1 < M)
                    *(float2*)(C + (size_t)r1 * DM + col) =
                        make_float2(acc[mi][ni][0] + b0, acc[mi][ni][1] + b1);
                if (r2 < M)
                    *(float2*)(C + (size_t)r2 * DM + col) =
                        make_float2(acc[mi][ni][2] + b0, acc[mi][ni][3] + b1);
            }
        }
    }
}

__global__ __launch_bounds__(256) void gemm_qkv_kernel(
    const __half* __restrict__ A,
    const __half* __restrict__ B0, const __half* __restrict__ B1,
    const __half* __restrict__ B2,
    const float* __restrict__ b0, const float* __restrict__ b1,
    const float* __restrict__ b2,
    __half* __restrict__ C0, __half* __restrict__ C1,
    __half* __restrict__ C2, int M)
{
    extern __shared__ __half smh[];
    const int z = blockIdx.z;
    const __half* Bt = (z == 0) ? B0 : (z == 1) ? B1 : B2;
    const float* bb  = (z == 0) ? b0 : (z == 1) ? b1 : b2;
    __half* C        = (z == 0) ? C0 : (z == 1) ? C1 : C2;
    gemm_core<true>(A, Bt, bb, C, M, smh);
}

__global__ __launch_bounds__(256) void gemm_f32out_kernel(
    const __half* __restrict__ A, const __half* __restrict__ Bt,
    const float* __restrict__ bias, float* __restrict__ C, int M)
{
    extern __shared__ __half smh[];
    gemm_core<false>(A, Bt, bias, C, M, smh);
}

// ---------------------------------------------------------------------------
// Fused RMSNorm + 3D RoPE on fp16 Q,K (in place). ATT_SCALE folded into Q.
// ---------------------------------------------------------------------------
__global__ __launch_bounds__(256) void rms_rope_kernel(
    __half* __restrict__ q, __half* __restrict__ k,
    const float* __restrict__ qscale, const float* __restrict__ kscale,
    const float* __restrict__ ft, const float* __restrict__ fh,
    const float* __restrict__ fw)
{
    const int n   = blockIdx.x;
    const int tid = threadIdx.x;
    __half2* q2 = (__half2*)(q + (size_t)n * DM);
    __half2* k2 = (__half2*)(k + (size_t)n * DM);

    float sq = 0.f, sk = 0.f;
#pragma unroll
    for (int i = tid; i < DM / 2; i += 256) {
        float2 a = __half22float2(q2[i]); sq += a.x * a.x + a.y * a.y;
        float2 b = __half22float2(k2[i]); sk += b.x * b.x + b.y * b.y;
    }
#pragma unroll
    for (int o = 16; o; o >>= 1) {
        sq += __shfl_xor_sync(0xffffffffu, sq, o);
        sk += __shfl_xor_sync(0xffffffffu, sk, o);
    }
    __shared__ float aq[8], ak[8];
    __shared__ float s_rq, s_rk;
    if ((tid & 31) == 0) { aq[tid >> 5] = sq; ak[tid >> 5] = sk; }
    __syncthreads();
    if (tid == 0) {
        float a = 0.f, b = 0.f;
#pragma unroll
        for (int i = 0; i < 8; ++i) { a += aq[i]; b += ak[i]; }
        s_rq = rsqrtf(a / (float)DM + 1e-6f);
        s_rk = rsqrtf(b / (float)DM + 1e-6f);
    }
    __syncthreads();
    const float rq = s_rq, rk = s_rk;

    const int wi = n % 15;
    const int hi = (n / 15) % 15;
    const int fi = n / 225;

    for (int pi = tid; pi < NH * (HD / 2); pi += 256) {
        const int p = pi & 63;
        float c, s;
        if (p < 22) {
            c = ft[(fi * 22 + p) * 2];
            s = ft[(fi * 22 + p) * 2 + 1];
        } else if (p < 43) {
            int pp = p - 22;
            c = fh[(hi * 21 + pp) * 2];
            s = fh[(hi * 21 + pp) * 2 + 1];
        } else {
            int pp = p - 43;
            c = fw[(wi * 21 + pp) * 2];
            s = fw[(wi * 21 + pp) * 2 + 1];
        }
        float2 xv = __half22float2(q2[pi]);
        float x0 = xv.x * rq * qscale[2 * pi];
        float x1 = xv.y * rq * qscale[2 * pi + 1];
        q2[pi] = __floats2half2_rn((x0 * c - x1 * s) * ATT_SCALE,
                                   (x0 * s + x1 * c) * ATT_SCALE);
        float2 yv = __half22float2(k2[pi]);
        float y0 = yv.x * rk * kscale[2 * pi];
        float y1 = yv.y * rk * kscale[2 * pi + 1];
        k2[pi] = __floats2half2_rn(y0 * c - y1 * s, y0 * s + y1 * c);
    }
}

// ---------------------------------------------------------------------------
// Flash attention, fp16 mma, FA2 register-P layout.
// 256 threads / 8 warps; warp w owns Q rows [w*16, w*16+16), ALL 64 KV cols.
// P never touches smem; row sums live in per-warp registers.
// KV double-buffered in smem via cp.async.
// ---------------------------------------------------------------------------
#define BQ 128
#define BKV 64
#define SQK 136    // smem stride (halves); 272 B rows -> conflict-free ldsm
#define Q_TILE_H (BQ * SQK)
#define KV_TILE_H (BKV * SQK)
#define ATT_SMEM_BYTES ((Q_TILE_H + 4 * KV_TILE_H) * 2)
#define NKT ((N_TOK + BKV - 1) / BKV)   // 46

__global__ __launch_bounds__(256, 1) void attn_kernel(
    const __half* __restrict__ Q, const __half* __restrict__ Kg,
    const __half* __restrict__ Vg, __half* __restrict__ O)
{
    extern __shared__ __half smh[];
    __half* Qs = smh;                                // 128 x 136
    __half* KVs = smh + Q_TILE_H;                    // [2 stages][K 64x136, V 64x136]

    const int tid  = threadIdx.x;
    const int lane = tid & 31;
    const int warp = tid >> 5;          // 0..7, owns rows warp*16..+15
    const int qr   = lane >> 2;
    const int qc   = lane & 3;
    const int head = blockIdx.y;
    const int q0   = blockIdx.x * BQ;

    const unsigned qbase  = smaddr(Qs);
    const unsigned kvbase = smaddr(KVs);
    const uint4 z4 = make_uint4(0, 0, 0, 0);

    // ---- load Q tile (plain vector stores) ----
#pragma unroll
    for (int l = 0; l < 8; ++l) {
        int idx = tid + l * 256;          // 0..2047 uint4
        int r = idx >> 4, c8 = (idx & 15) * 8;
        int t = q0 + r;
        uint4 v = (t < N_TOK)
                      ? *(const uint4*)(Q + (size_t)t * DM + head * HD + c8) : z4;
        *(uint4*)(Qs + r * SQK + c8) = v;
    }

    // ---- issue KV tiles 0 and 1 via cp.async ----
#pragma unroll
    for (int s = 0; s < 2; ++s) {
        const int kv0 = s * BKV;
        unsigned kdst = kvbase + (unsigned)(s * 2 * KV_TILE_H) * 2u;
        unsigned vdst = kdst + (unsigned)KV_TILE_H * 2u;
#pragma unroll
        for (int l = 0; l < 4; ++l) {
            int idx = tid + l * 256;       // 0..1023
            int r = idx >> 4, c8 = (idx & 15) * 8;
            int t = kv0 + r;               // always < N_TOK for tiles 0,1
            cp16(kdst + (unsigned)(r * SQK + c8) * 2u,
                 Kg + (size_t)t * DM + head * HD + c8, 16u);
            cp16(vdst + (unsigned)(r * SQK + c8) * 2u,
                 Vg + (size_t)t * DM + head * HD + c8, 16u);
        }
        asm volatile("cp.async.commit_group;" ::: "memory");
    }

    __syncthreads();   // Q visible

    // ---- hoist Q fragments into registers (8 k-chunks x 4 regs) ----
    unsigned qfrag[8][4];
#pragma unroll
    for (int kb = 0; kb < 8; ++kb)
        ld_afrag(qfrag[kb], qbase, warp * 16, kb * 16, SQK, lane);

    float acc_o[16][4];
#pragma unroll
    for (int ni = 0; ni < 16; ++ni)
#pragma unroll
        for (int t = 0; t < 4; ++t) acc_o[ni][t] = 0.f;
    float suml0 = 0.f, suml1 = 0.f;

    for (int kt = 0; kt < NKT; ++kt) {
        if (kt + 1 < NKT)
            asm volatile("cp.async.wait_group 1;" ::: "memory");
        else
            asm volatile("cp.async.wait_group 0;" ::: "memory");
        __syncthreads();   // stage kt&1 ready for all

        const int st = kt & 1;
        const unsigned kst = kvbase + (unsigned)(st * 2 * KV_TILE_H) * 2u;
        const unsigned vst = kst + (unsigned)KV_TILE_H * 2u;
        const int rem = N_TOK - kt * BKV;

        // ---- S = Q @ K^T : 8 n8-frags over 64 cols ----
        float acc_s[8][4];
#pragma unroll
        for (int ni = 0; ni < 8; ++ni)
#pragma unroll
            for (int t = 0; t < 4; ++t) acc_s[ni][t] = 0.f;

#pragma unroll
        for (int kb = 0; kb < 8; ++kb) {
            unsigned b[8][2];
#pragma unroll
            for (int g = 0; g < 4; ++g)
                ld_bfrag2(b[2 * g], b[2 * g + 1], kst, g * 16, kb * 16,
                          SQK, lane);
#pragma unroll
            for (int ni = 0; ni < 8; ++ni)
                mma_f16(acc_s[ni], qfrag[kb], b[ni]);
        }

        // ---- exp(s - SHIFT) in registers -> P fragments ----
        unsigned pl[8], ph[8];
#pragma unroll
        for (int ni = 0; ni < 8; ++ni) {
            int col = ni * 8 + 2 * qc;
            float e0 = __expf(acc_s[ni][0] - EXP_SHIFT);
            float e1 = __expf(acc_s[ni][1] - EXP_SHIFT);
            float e2 = __expf(acc_s[ni][2] - EXP_SHIFT);
            float e3 = __expf(acc_s[ni][3] - EXP_SHIFT);
            if (rem < BKV) {
                if (col     >= rem) { e0 = 0.f; e2 = 0.f; }
                if (col + 1 >= rem) { e1 = 0.f; e3 = 0.f; }
            }
            suml0 += e0 + e1;
            suml1 += e2 + e3;
            __half2 h01 = __floats2half2_rn(e0, e1);
            __half2 h23 = __floats2half2_rn(e2, e3);
            pl[ni] = *(unsigned*)&h01;
            ph[ni] = *(unsigned*)&h23;
        }

        // ---- O += P @ V : P from registers, V via ldmatrix.trans ----
#pragma unroll
        for (int kc = 0; kc < 4; ++kc) {
            unsigned a[4];
            a[0] = pl[2 * kc];      // rows qr,   k = 2qc..2qc+1
            a[1] = ph[2 * kc];      // rows qr+8
            a[2] = pl[2 * kc + 1];  // rows qr,   k = 2qc+8..
            a[3] = ph[2 * kc + 1];
#pragma unroll
            for (int g = 0; g < 8; ++g) {
                unsigned b[2][2];
                ld_bfrag2_t(b[0], b[1], vst, g * 16, kc * 16, SQK, lane);
                mma_f16(acc_o[2 * g],     a, b[0]);
                mma_f16(acc_o[2 * g + 1], a, b[1]);
            }
        }

        __syncthreads();   // all warps done reading stage st

        // ---- issue tile kt+2 into stage st ----
        if (kt + 2 < NKT) {
            const int kv0 = (kt + 2) * BKV;
            unsigned kdst = kst;
            unsigned vdst = vst;
#pragma unroll
            for (int l = 0; l < 4; ++l) {
                int idx = tid + l * 256;
                int r = idx >> 4, c8 = (idx & 15) * 8;
                int t = kv0 + r;
                unsigned bytes = (t < N_TOK) ? 16u : 0u;
                const __half* ks = Kg + (size_t)(t < N_TOK ? t : 0) * DM
                                      + head * HD + c8;
                const __half* vs = Vg + (size_t)(t < N_TOK ? t : 0) * DM
                                      + head * HD + c8;
                cp16(kdst + (unsigned)(r * SQK + c8) * 2u, ks, bytes);
                cp16(vdst + (unsigned)(r * SQK + c8) * 2u, vs, bytes);
            }
            asm volatile("cp.async.commit_group;" ::: "memory");
        }
    }

    // ---- reduce row sums across qc lanes (rows fully warp-owned) ----
    suml0 += __shfl_xor_sync(0xffffffffu, suml0, 1);
    suml0 += __shfl_xor_sync(0xffffffffu, suml0, 2);
    suml1 += __shfl_xor_sync(0xffffffffu, suml1, 1);
    suml1 += __shfl_xor_sync(0xffffffffu, suml1, 2);
    const float inv0 = 1.f / suml0;
    const float inv1 = 1.f / suml1;

    // ---- write O ----
    {
        int r1 = warp * 16 + qr;
        int t1 = q0 + r1, t2 = t1 + 8;
#pragma unroll
        for (int ni = 0; ni < 16; ++ni) {
            int col = ni * 8 + 2 * qc;
            if (t1 < N_TOK)
                *(__half2*)(O + (size_t)t1 * DM + head * HD + col) =
                    __floats2half2_rn(acc_o[ni][0] * inv0, acc_o[ni][1] * inv0);
            if (t2 < N_TOK)
                *(__half2*)(O + (size_t)t2 * DM + head * HD + col) =
                    __floats2half2_rn(acc_o[ni][2] * inv1, acc_o[ni][3] * inv1);
        }
    }
}

// ---------------------------------------------------------------------------
extern "C" void kernel_launch(void* const* d_in, const int* in_sizes, int n_in,
                              void* d_out, int out_size)
{
    const float* x  = (const float*)d_in[0];
    const float* Wq = (const float*)d_in[1];
    const float* bq = (const float*)d_in[2];
    const float* Wk = (const float*)d_in[3];
    const float* bk = (const float*)d_in[4];
    const float* Wv = (const float*)d_in[5];
    const float* bv = (const float*)d_in[6];
    const float* Wo = (const float*)d_in[7];
    const float* bo = (const float*)d_in[8];
    const float* qs = (const float*)d_in[9];
    const float* ks = (const float*)d_in[10];
    const float* ft = (const float*)d_in[11];
    const float* fh = (const float*)d_in[12];
    const float* fw = (const float*)d_in[13];
    float* out = (float*)d_out;

    __half *xh, *qh, *kh, *vh, *oh, *wqt, *wkt, *wvt, *wot;
    cudaGetSymbolAddress((void**)&xh, g_xh);
    cudaGetSymbolAddress((void**)&qh, g_qh);
    cudaGetSymbolAddress((void**)&kh, g_kh);
    cudaGetSymbolAddress((void**)&vh, g_vh);
    cudaGetSymbolAddress((void**)&oh, g_oh);
    cudaGetSymbolAddress((void**)&wqt, g_wqt);
    cudaGetSymbolAddress((void**)&wkt, g_wkt);
    cudaGetSymbolAddress((void**)&wvt, g_wvt);
    cudaGetSymbolAddress((void**)&wot, g_wot);

    cudaFuncSetAttribute(gemm_qkv_kernel,
                         cudaFuncAttributeMaxDynamicSharedMemorySize,
                         GEMM_SMEM_BYTES);
    cudaFuncSetAttribute(gemm_f32out_kernel,
                         cudaFuncAttributeMaxDynamicSharedMemorySize,
                         GEMM_SMEM_BYTES);
    cudaFuncSetAttribute(attn_kernel,
                         cudaFuncAttributeMaxDynamicSharedMemorySize,
                         ATT_SMEM_BYTES);

    // conversions
    const int n4 = N_TOK * DM / 4;
    convert_x_kernel<<<(n4 + 255) / 256, 256>>>(x, xh, n4);
    dim3 tb(32, 8), tg(DM / 32, DM / 32, 4);
    transpose_w4_kernel<<<tg, tb>>>(Wq, Wk, Wv, Wo, wqt, wkt, wvt, wot);

    // Q,K,V projections in one launch
    dim3 gq(DM / 128, (N_TOK + 127) / 128, 3);
    gemm_qkv_kernel<<<gq, 256, GEMM_SMEM_BYTES>>>(
        xh, wqt, wkt, wvt, bq, bk, bv, qh, kh, vh, N_TOK);

    rms_rope_kernel<<<N_TOK, 256>>>(qh, kh, qs, ks, ft, fh, fw);

    dim3 ga((N_TOK + BQ - 1) / BQ, NH);
    attn_kernel<<<ga, 256, ATT_SMEM_BYTES>>>(qh, kh, vh, oh);

    dim3 gg(DM / 128, (N_TOK + 127) / 128);
    gemm_f32out_kernel<<<gg, 256, GEMM_SMEM_BYTES>>>(oh, wot, bo, out, N_TOK);
}